// round 14
// baseline (speedup 1.0000x reference)
#include <cuda_runtime.h>
#include <cuda_bf16.h>
#include <math.h>
#include <stdint.h>

#define BB 2
#define NN 2048
#define DD 1024
#define HH 16
#define HCC 8
#define HID 4096
#define BN (BB*NN)

// ------------------------- scratch ----------------------------------------------
__device__ float g_emb[BB*HID];
__device__ float g_p1[64*2*HID];
__device__ float g_p2[64*2*HID];
__device__ float g_p3[2*64*2*HID];             // also reused as chS split-K partials
__device__ float g_av[BB*HID];
__device__ float g_cv[BB*HID];
__device__ __nv_bfloat16 g_wbf[6u*1048576u];   // transposed bf16 weights [n][k]
__device__ __nv_bfloat16 g_x1[BN*DD];
__device__ __nv_bfloat16 g_qk[BN*DD];
__device__ __nv_bfloat16 g_v[BN*DD];
__device__ float g_phi[BB*NN];
__device__ __nv_bfloat16 g_attn[BN*DD];
__device__ float g_xmid[BN*DD];
__device__ __nv_bfloat16 g_x2[BN*DD];
__device__ __nv_bfloat16 g_qkc[BN*DD];
__device__ __nv_bfloat16 g_vc[BN*DD];
__device__ __nv_bfloat16 g_Pc[BB*HCC*128*128];
__device__ __nv_bfloat16 g_ch[BN*DD];

// ------------------------- helpers ---------------------------------------------
__device__ inline float blockRed(float v, int op) {
    __shared__ float sm[32];
    int lane = threadIdx.x & 31, w = threadIdx.x >> 5;
    #pragma unroll
    for (int o = 16; o; o >>= 1) {
        float t = __shfl_xor_sync(0xffffffffu, v, o);
        v = op ? fmaxf(v, t) : v + t;
    }
    if (lane == 0) sm[w] = v;
    __syncthreads();
    int nw = blockDim.x >> 5;
    if (w == 0) {
        v = (lane < nw) ? sm[lane] : (op ? -INFINITY : 0.f);
        #pragma unroll
        for (int o = 16; o; o >>= 1) {
            float t = __shfl_xor_sync(0xffffffffu, v, o);
            v = op ? fmaxf(v, t) : v + t;
        }
        if (lane == 0) sm[0] = v;
    }
    __syncthreads();
    float r = sm[0];
    __syncthreads();
    return r;
}

__device__ inline void mma16816(float* c, const uint32_t* a, const uint32_t* b) {
    asm volatile(
        "mma.sync.aligned.m16n8k16.row.col.f32.bf16.bf16.f32 "
        "{%0,%1,%2,%3}, {%4,%5,%6,%7}, {%8,%9}, {%0,%1,%2,%3};\n"
        : "+f"(c[0]), "+f"(c[1]), "+f"(c[2]), "+f"(c[3])
        : "r"(a[0]), "r"(a[1]), "r"(a[2]), "r"(a[3]), "r"(b[0]), "r"(b[1]));
}

__device__ inline void ldsm_x4(uint32_t* r, uint32_t saddr) {
    asm volatile("ldmatrix.sync.aligned.m8n8.x4.shared.b16 {%0,%1,%2,%3}, [%4];"
        : "=r"(r[0]), "=r"(r[1]), "=r"(r[2]), "=r"(r[3]) : "r"(saddr));
}

__device__ inline void ldsm_x4_t(uint32_t* r, uint32_t saddr) {
    asm volatile("ldmatrix.sync.aligned.m8n8.x4.trans.shared.b16 {%0,%1,%2,%3}, [%4];"
        : "=r"(r[0]), "=r"(r[1]), "=r"(r[2]), "=r"(r[3]) : "r"(saddr));
}

__device__ inline uint32_t packbf(float a, float b) {
    __nv_bfloat162 t = __floats2bfloat162_rn(a, b);
    return *(uint32_t*)&t;
}

__device__ inline uint32_t smem_u32(const void* p) {
    uint32_t a;
    asm("{ .reg .u64 t; cvta.to.shared.u64 t, %1; cvt.u32.u64 %0, t; }" : "=r"(a) : "l"(p));
    return a;
}

__device__ inline void cp_async16(uint32_t saddr, const void* gaddr) {
    asm volatile("cp.async.cg.shared.global [%0], [%1], 16;" :: "r"(saddr), "l"(gaddr));
}

// ------------------------- small kernels ----------------------------------------
__global__ void k_emb(const float* __restrict__ t, float* __restrict__ emb) {
    int i = blockIdx.x * 256 + threadIdx.x;
    if (i >= BB * HID) return;
    int b = i / HID, j = i % HID;
    int jj = j & 2047;
    float f = expf(-9.210340371976184f * (float)jj / 2048.0f);
    float a = t[b] * f;
    emb[i] = (j < 2048) ? cosf(a) : sinf(a);
}

// split-K GEMV partials: 64 k-slices of 64, scalar coalesced loads, 1024 CTAs
__global__ void k_gemv_part(const float* __restrict__ in, const float* __restrict__ W,
                            float* __restrict__ part) {
    int col = blockIdx.x * 256 + threadIdx.x;
    int k0 = blockIdx.y * 64;
    float a0 = 0.f, a1 = 0.f;
    #pragma unroll 16
    for (int k = k0; k < k0 + 64; k++) {
        float w = W[(long)k * HID + col];
        a0 += in[k] * w;
        a1 += in[HID + k] * w;
    }
    part[((long)blockIdx.y * 2 + 0) * HID + col] = a0;
    part[((long)blockIdx.y * 2 + 1) * HID + col] = a1;
}

// fused: reduce prev partials (+bias, silu) for this 64-k-slice, then partial GEMV
__global__ void k_gemv_step(const float* __restrict__ prevPart,
                            const float* __restrict__ prevBias,
                            const float* __restrict__ W0, const float* __restrict__ W1,
                            float* __restrict__ outPart) {
    __shared__ float in_s[2][64];
    const float* W = blockIdx.z ? W1 : W0;
    float* op = outPart + (long)blockIdx.z * 64 * 2 * HID;
    int tid = threadIdx.x;
    int k0 = blockIdx.y * 64;
    if (tid < 128) {
        int b = tid >> 6, kk = tid & 63, k = k0 + kk;
        float s = prevBias[k];
        #pragma unroll 16
        for (int p2 = 0; p2 < 64; p2++) s += prevPart[((long)p2 * 2 + b) * HID + k];
        in_s[b][kk] = s / (1.f + __expf(-s));
    }
    __syncthreads();
    int col = blockIdx.x * 256 + tid;
    float a0 = 0.f, a1 = 0.f;
    #pragma unroll 16
    for (int kk = 0; kk < 64; kk++) {
        float w = W[(long)(k0 + kk) * HID + col];
        a0 += in_s[0][kk] * w;
        a1 += in_s[1][kk] * w;
    }
    op[((long)blockIdx.y * 2 + 0) * HID + col] = a0;
    op[((long)blockIdx.y * 2 + 1) * HID + col] = a1;
}

__global__ void k_gemv_red2(const float* __restrict__ part, const float* __restrict__ b0,
                            const float* __restrict__ b1, float* __restrict__ o0,
                            float* __restrict__ o1) {
    int i = blockIdx.x * 256 + threadIdx.x;
    if (i >= 2 * HID) return;
    const float* pp = part + (long)blockIdx.z * 64 * 2 * HID;
    const float* bias = blockIdx.z ? b1 : b0;
    float* out = blockIdx.z ? o1 : o0;
    int b = i / HID, col = i % HID;
    float s = bias[col];
    #pragma unroll 8
    for (int p = 0; p < 64; p++) s += pp[((long)p * 2 + b) * HID + col];
    out[(long)b * HID + col] = s;
}

// tiled transpose + fp32->bf16
__global__ void k_convt(const float* __restrict__ w0, const float* __restrict__ w1,
                        const float* __restrict__ w2, const float* __restrict__ w3,
                        const float* __restrict__ w4, const float* __restrict__ w5,
                        __nv_bfloat16* __restrict__ out) {
    __shared__ float t[32][33];
    const float* s = w0;
    int z = blockIdx.z;
    if (z == 1) s = w1; else if (z == 2) s = w2; else if (z == 3) s = w3;
    else if (z == 4) s = w4; else if (z == 5) s = w5;
    int x = blockIdx.x * 32 + threadIdx.x;
    int y0 = blockIdx.y * 32;
    #pragma unroll
    for (int j = 0; j < 32; j += 8)
        t[threadIdx.y + j][threadIdx.x] = s[(long)(y0 + threadIdx.y + j) * DD + x];
    __syncthreads();
    __nv_bfloat16* d = out + (long)z * 1048576;
    int n = blockIdx.x * 32 + threadIdx.y;
    int k = y0 + threadIdx.x;
    #pragma unroll
    for (int j = 0; j < 32; j += 8)
        d[(long)(n + j) * DD + k] = __float2bfloat16(t[threadIdx.x][threadIdx.y + j]);
}

// LayerNorm + modulate -> bf16, optional fused phi (doob) reduction
__global__ void k_ln_mod(const float* __restrict__ xin, __nv_bfloat16* __restrict__ xout,
                         const float* __restrict__ sc, const float* __restrict__ bi,
                         const float* __restrict__ mod, const float* __restrict__ dw,
                         const float* __restrict__ db, float* __restrict__ phi) {
    int r = blockIdx.x;
    int b = r >> 11;
    const float* xr = xin + (long)r * DD;
    int tid = threadIdx.x;
    float v[4];
    float s = 0.f;
    #pragma unroll
    for (int i = 0; i < 4; i++) { v[i] = xr[tid + i * 256]; s += v[i]; }
    s = blockRed(s, 0);
    float mu = s * (1.0f / DD);
    float vs = 0.f;
    #pragma unroll
    for (int i = 0; i < 4; i++) { float d = v[i] - mu; vs += d * d; }
    vs = blockRed(vs, 0);
    float rstd = rsqrtf(vs * (1.0f / DD) + 1e-6f);
    float ps = 0.f;
    #pragma unroll
    for (int i = 0; i < 4; i++) {
        int j = tid + i * 256;
        float y = (v[i] - mu) * rstd * sc[j] + bi[j];
        float m = y * (1.f + mod[(long)b * HID + 1024 + j]) + mod[(long)b * HID + j];
        xout[(long)r * DD + j] = __float2bfloat16(m);
        if (dw) ps += m * dw[j];
    }
    if (dw) {
        ps = blockRed(ps, 0);
        if (tid == 0) phi[r] = ps + db[0];
    }
}

// ------------------------- channel S: split-K Gram partials ----------------------
__global__ void __launch_bounds__(256) k_chS_part(
    const __nv_bfloat16* __restrict__ qkc, float* __restrict__ Spart)
{
    __shared__ __nv_bfloat16 sQt[128 * 72];
    int z = blockIdx.x, sl = blockIdx.y;
    int b = z >> 3, hc = z & 7;
    int tid = threadIdx.x, wid = tid >> 5, lane = tid & 31;
    int g = lane >> 2, tg = lane & 3;
    int wm = (wid & 1) * 64, wn = (wid >> 1) * 32;
    const __nv_bfloat16* base = qkc + ((long)b * NN + sl * 512) * DD + hc * 128;

    int arow = lane & 15, ak = (lane & 16) ? 8 : 0;
    int brow = (lane & 7) + ((lane & 16) ? 8 : 0), bk = (lane & 8) ? 8 : 0;

    float acc[4][4][4];
    #pragma unroll
    for (int i = 0; i < 4; i++)
        #pragma unroll
        for (int j = 0; j < 4; j++)
            #pragma unroll
            for (int q = 0; q < 4; q++) acc[i][j][q] = 0.f;

    uint4 rq[4];
    #pragma unroll
    for (int t = 0; t < 4; t++) {
        int idx = tid + t * 256;
        int tok = idx >> 4, dg = (idx & 15) * 8;
        rq[t] = *(const uint4*)(base + (long)tok * DD + dg);
    }

    for (int ch = 0; ch < 8; ch++) {
        #pragma unroll
        for (int t = 0; t < 4; t++) {
            int idx = tid + t * 256;
            int tok = idx >> 4, dg = (idx & 15) * 8;
            union { uint4 u; __nv_bfloat16 hh[8]; } tv;
            tv.u = rq[t];
            #pragma unroll
            for (int j = 0; j < 8; j++) sQt[(dg + j) * 72 + tok] = tv.hh[j];
        }
        __syncthreads();
        if (ch < 7) {
            #pragma unroll
            for (int t = 0; t < 4; t++) {
                int idx = tid + t * 256;
                int tok = idx >> 4, dg = (idx & 15) * 8;
                rq[t] = *(const uint4*)(base + (long)((ch + 1) * 64 + tok) * DD + dg);
            }
        }
        #pragma unroll
        for (int kk = 0; kk < 64; kk += 16) {
            uint32_t ar[4][4], br[4][2];
            #pragma unroll
            for (int mi = 0; mi < 4; mi++)
                ldsm_x4(ar[mi], smem_u32(&sQt[(wm + mi * 16 + arow) * 72 + kk + ak]));
            #pragma unroll
            for (int np = 0; np < 2; np++) {
                uint32_t rr[4];
                ldsm_x4(rr, smem_u32(&sQt[(wn + np * 16 + brow) * 72 + kk + bk]));
                br[2 * np][0] = rr[0]; br[2 * np][1] = rr[1];
                br[2 * np + 1][0] = rr[2]; br[2 * np + 1][1] = rr[3];
            }
            #pragma unroll
            for (int mi = 0; mi < 4; mi++)
                #pragma unroll
                for (int ni = 0; ni < 4; ni++)
                    mma16816(acc[mi][ni], ar[mi], br[ni]);
        }
        __syncthreads();
    }

    float* dst = Spart + ((long)z * 4 + sl) * 16384;
    #pragma unroll
    for (int mi = 0; mi < 4; mi++)
        #pragma unroll
        for (int ni = 0; ni < 4; ni++) {
            int r0 = wm + mi * 16 + g, c0 = wn + ni * 8 + 2 * tg;
            dst[r0 * 128 + c0] = acc[mi][ni][0];
            dst[r0 * 128 + c0 + 1] = acc[mi][ni][1];
            dst[(r0 + 8) * 128 + c0] = acc[mi][ni][2];
            dst[(r0 + 8) * 128 + c0 + 1] = acc[mi][ni][3];
        }
}

// combine partials + diag-q2 + softmax -> Pc (grid 16)
#define CHR_SMEM (128*129*4 + 512)
__global__ void __launch_bounds__(256) k_chS_red(
    const float* __restrict__ Spart, const float* __restrict__ tau,
    __nv_bfloat16* __restrict__ Pc)
{
    extern __shared__ __align__(16) char smraw[];
    float* sS = (float*)smraw;
    float* sq2 = (float*)(smraw + 128 * 129 * 4);
    int z = blockIdx.x;
    int hc = z & 7;
    int tid = threadIdx.x, wid = tid >> 5, lane = tid & 31;
    float ft = 0.022097086912079608f * tau[hc];
    const float* src = Spart + (long)z * 4 * 16384;

    for (int idx = tid; idx < 16384; idx += 256) {
        float s = src[idx] + src[16384 + idx] + src[2 * 16384 + idx] + src[3 * 16384 + idx];
        sS[(idx >> 7) * 129 + (idx & 127)] = s;
    }
    __syncthreads();
    if (tid < 128) sq2[tid] = sS[tid * 129 + tid];
    __syncthreads();

    for (int it = 0; it < 16; it++) {
        int r = it * 8 + wid;
        float v[4], mx = -1e30f;
        #pragma unroll
        for (int j = 0; j < 4; j++) {
            int c = lane + 32 * j;
            v[j] = (2.f * sS[r * 129 + c] - sq2[c]) * ft;
            mx = fmaxf(mx, v[j]);
        }
        #pragma unroll
        for (int o = 16; o; o >>= 1) mx = fmaxf(mx, __shfl_xor_sync(0xffffffffu, mx, o));
        float sum = 0.f;
        #pragma unroll
        for (int j = 0; j < 4; j++) { v[j] = __expf(v[j] - mx); sum += v[j]; }
        #pragma unroll
        for (int o = 16; o; o >>= 1) sum += __shfl_xor_sync(0xffffffffu, sum, o);
        float inv = 1.f / sum;
        #pragma unroll
        for (int j = 0; j < 4; j++)
            Pc[(long)z * 16384 + r * 128 + lane + 32 * j] = __float2bfloat16(v[j] * inv);
    }
}

// ------------------------- flash token attention (fused bias) --------------------
// logits_eff[m,n] = 2*q_m.q_n + phi[b,n] - |q_n|^2 ; q2 computed from resident K tile
__global__ void __launch_bounds__(256) k_flash(
    const __nv_bfloat16* __restrict__ qk,
    const __nv_bfloat16* __restrict__ v,
    const float* __restrict__ phi,
    __nv_bfloat16* __restrict__ out)
{
    int z = blockIdx.z;
    int b = z >> 4, h = z & 15;
    const __nv_bfloat16* Qb = qk + ((long)b * NN) * DD + h * 64;
    const __nv_bfloat16* Vb = v  + ((long)b * NN) * DD + h * 64;
    const float* phib = phi + (long)b * NN;
    int m0 = blockIdx.y * 128;

    __shared__ __nv_bfloat16 sK[128][72];
    __shared__ __nv_bfloat16 sVn[128][72];
    __shared__ float sBias[128];

    int tid = threadIdx.x, wid = tid >> 5, lane = tid & 31;
    int g = lane >> 2, tg = lane & 3;
    int mrow = m0 + wid * 16;

    int brow = (lane & 7) + ((lane & 16) ? 8 : 0), bk = (lane & 8) ? 8 : 0;
    int vrow = (lane & 7) + ((lane & 8) ? 8 : 0), vcol = (lane & 16) ? 8 : 0;

    uint32_t qf[4][4];
    #pragma unroll
    for (int kp = 0; kp < 4; kp++) {
        const __nv_bfloat16* q0 = Qb + (long)(mrow + g) * DD + kp * 16 + 2 * tg;
        const __nv_bfloat16* q1 = Qb + (long)(mrow + g + 8) * DD + kp * 16 + 2 * tg;
        qf[kp][0] = *(const uint32_t*)q0;
        qf[kp][1] = *(const uint32_t*)q1;
        qf[kp][2] = *(const uint32_t*)(q0 + 8);
        qf[kp][3] = *(const uint32_t*)(q1 + 8);
    }

    uint4 rk[4], rv[4];
    #pragma unroll
    for (int t = 0; t < 4; t++) {
        int i = tid + t * 256;
        int tok = i >> 3, dv = (i & 7) * 8;
        rk[t] = *(const uint4*)(Qb + (long)tok * DD + dv);
        rv[t] = *(const uint4*)(Vb + (long)tok * DD + dv);
    }

    float m_run[2] = {-1e30f, -1e30f};
    float l_run[2] = {0.f, 0.f};
    float o[8][4];
    #pragma unroll
    for (int i = 0; i < 8; i++)
        #pragma unroll
        for (int j = 0; j < 4; j++) o[i][j] = 0.f;

    for (int n0 = 0; n0 < NN; n0 += 128) {
        #pragma unroll
        for (int t = 0; t < 4; t++) {
            int i = tid + t * 256;
            int tok = i >> 3, dv = (i & 7) * 8;
            *(uint4*)&sK[tok][dv] = rk[t];
            *(uint4*)&sVn[tok][dv] = rv[t];
        }
        __syncthreads();

        if (n0 + 128 < NN) {
            #pragma unroll
            for (int t = 0; t < 4; t++) {
                int i = tid + t * 256;
                int tok = i >> 3, dv = (i & 7) * 8;
                rk[t] = *(const uint4*)(Qb + (long)(n0 + 128 + tok) * DD + dv);
                rv[t] = *(const uint4*)(Vb + (long)(n0 + 128 + tok) * DD + dv);
            }
        }

        // fused bias: sBias[n] = phi[n0+n] - |k_n|^2 (from resident tile)
        if (tid < 128) {
            const uint4* row = (const uint4*)&sK[tid][0];
            float q2 = 0.f;
            #pragma unroll
            for (int u = 0; u < 8; u++) {
                union { uint4 u4; __nv_bfloat16 hh[8]; } tv;
                tv.u4 = row[u];
                #pragma unroll
                for (int j = 0; j < 8; j++) {
                    float f = __bfloat162float(tv.hh[j]);
                    q2 += f * f;
                }
            }
            sBias[tid] = phib[n0 + tid] - q2;
        }

        float s[16][4];
        #pragma unroll
        for (int ni = 0; ni < 16; ni++)
            s[ni][0] = s[ni][1] = s[ni][2] = s[ni][3] = 0.f;
        #pragma unroll
        for (int kp = 0; kp < 4; kp++) {
            #pragma unroll
            for (int np = 0; np < 8; np++) {
                uint32_t rr[4];
                ldsm_x4(rr, smem_u32(&sK[np * 16 + brow][kp * 16 + bk]));
                uint32_t b0[2] = { rr[0], rr[1] }, b1[2] = { rr[2], rr[3] };
                mma16816(s[2 * np], qf[kp], b0);
                mma16816(s[2 * np + 1], qf[kp], b1);
            }
        }
        __syncthreads();   // sBias visibility

        float mx[2] = {-1e30f, -1e30f};
        #pragma unroll
        for (int ni = 0; ni < 16; ni++) {
            #pragma unroll
            for (int j = 0; j < 4; j++) {
                float bval = sBias[ni * 8 + 2 * tg + (j & 1)];
                s[ni][j] = 2.f * s[ni][j] + bval;
                mx[j >> 1] = fmaxf(mx[j >> 1], s[ni][j]);
            }
        }
        #pragma unroll
        for (int r = 0; r < 2; r++) {
            mx[r] = fmaxf(mx[r], __shfl_xor_sync(0xffffffffu, mx[r], 1));
            mx[r] = fmaxf(mx[r], __shfl_xor_sync(0xffffffffu, mx[r], 2));
        }
        float m_new[2], alpha[2], rs[2] = {0.f, 0.f};
        #pragma unroll
        for (int r = 0; r < 2; r++) {
            m_new[r] = fmaxf(m_run[r], mx[r]);
            alpha[r] = __expf(m_run[r] - m_new[r]);
            m_run[r] = m_new[r];
        }
        #pragma unroll
        for (int ni = 0; ni < 16; ni++) {
            #pragma unroll
            for (int j = 0; j < 4; j++) {
                float p = __expf(s[ni][j] - m_new[j >> 1]);
                s[ni][j] = p;
                rs[j >> 1] += p;
            }
        }
        #pragma unroll
        for (int r = 0; r < 2; r++) {
            rs[r] += __shfl_xor_sync(0xffffffffu, rs[r], 1);
            rs[r] += __shfl_xor_sync(0xffffffffu, rs[r], 2);
            l_run[r] = l_run[r] * alpha[r] + rs[r];
        }
        #pragma unroll
        for (int di = 0; di < 8; di++) {
            o[di][0] *= alpha[0]; o[di][1] *= alpha[0];
            o[di][2] *= alpha[1]; o[di][3] *= alpha[1];
        }
        uint32_t pf[8][4];
        #pragma unroll
        for (int kp = 0; kp < 8; kp++) {
            pf[kp][0] = packbf(s[2 * kp][0], s[2 * kp][1]);
            pf[kp][1] = packbf(s[2 * kp][2], s[2 * kp][3]);
            pf[kp][2] = packbf(s[2 * kp + 1][0], s[2 * kp + 1][1]);
            pf[kp][3] = packbf(s[2 * kp + 1][2], s[2 * kp + 1][3]);
        }
        #pragma unroll
        for (int kp = 0; kp < 8; kp++) {
            #pragma unroll
            for (int dp = 0; dp < 4; dp++) {
                uint32_t rr[4];
                ldsm_x4_t(rr, smem_u32(&sVn[kp * 16 + vrow][dp * 16 + vcol]));
                uint32_t b0[2] = { rr[0], rr[1] }, b1[2] = { rr[2], rr[3] };
                mma16816(o[2 * dp], pf[kp], b0);
                mma16816(o[2 * dp + 1], pf[kp], b1);
            }
        }
        __syncthreads();
    }

    float inv0 = 1.f / l_run[0], inv1 = 1.f / l_run[1];
    long r0 = (long)(b * NN + mrow + g) * DD + h * 64;
    long r1 = (long)(b * NN + mrow + g + 8) * DD + h * 64;
    #pragma unroll
    for (int di = 0; di < 8; di++) {
        int col = di * 8 + 2 * tg;
        __nv_bfloat162 v0 = __floats2bfloat162_rn(o[di][0] * inv0, o[di][1] * inv0);
        __nv_bfloat162 v1 = __floats2bfloat162_rn(o[di][2] * inv1, o[di][3] * inv1);
        *(__nv_bfloat162*)&out[r0 + col] = v0;
        *(__nv_bfloat162*)&out[r1 + col] = v1;
    }
}

// ------------------------- generalized fast GEMM (cp.async + ldmatrix) ----------
struct GemmF {
    const __nv_bfloat16 *A, *B;
    long sA, sB, sC;
    long bBz;
    int K;
    void *C, *C2;
    int epi;                   // 0 exp bf16, 1 bf16, 3 residual fp32, 5 pair
    int zmode;
    const float *e0, *e1, *e2;
};

#define GF_SMEM (4*128*72*2)

__global__ void __launch_bounds__(256, 2) k_gemmF(GemmF p) {
    extern __shared__ __nv_bfloat16 smdyn[];
    __nv_bfloat16* sA[2] = { smdyn, smdyn + 128 * 72 };
    __nv_bfloat16* sB[2] = { smdyn + 2 * 128 * 72, smdyn + 3 * 128 * 72 };
    int tid = threadIdx.x, wid = tid >> 5, lane = tid & 31;
    int g = lane >> 2, tg = lane & 3;
    int bm = blockIdx.y * 128, bn = blockIdx.x * 128;
    int wm = (wid & 1) * 64, wn = (wid >> 1) * 32;

    int arow = lane & 15, ak = (lane & 16) ? 8 : 0;
    int brow = (lane & 7) + ((lane & 16) ? 8 : 0), bk = (lane & 8) ? 8 : 0;

    long offA = 0, offB = 0, offC = 0;
    if (p.zmode == 1) {
        int z = blockIdx.z, b = z >> 3, hc = z & 7;
        offA = (long)b * NN * DD + hc * 128;
        offB = (long)z * p.bBz;
        offC = offA;
    }
    const __nv_bfloat16* Ag = p.A + offA + (long)bm * p.sA;
    const __nv_bfloat16* Bg = p.B + offB + (long)bn * p.sB;

    float acc[4][4][4];
    #pragma unroll
    for (int i = 0; i < 4; i++)
        #pragma unroll
        for (int j = 0; j < 4; j++)
            #pragma unroll
            for (int q = 0; q < 4; q++) acc[i][j][q] = 0.f;

    #pragma unroll
    for (int t = 0; t < 4; t++) {
        int idx = tid + t * 256;
        int row = idx >> 3, v = (idx & 7) * 8;
        cp_async16(smem_u32(&sA[0][row * 72 + v]), Ag + (long)row * p.sA + v);
        cp_async16(smem_u32(&sB[0][row * 72 + v]), Bg + (long)row * p.sB + v);
    }
    asm volatile("cp.async.commit_group;");

    int nc = p.K >> 6;
    #pragma unroll 1
    for (int c = 0; c < nc; c++) {
        int s = c & 1;
        if (c < nc - 1) {
            int s2 = s ^ 1, k0 = (c + 1) * 64;
            #pragma unroll
            for (int t = 0; t < 4; t++) {
                int idx = tid + t * 256;
                int row = idx >> 3, v = (idx & 7) * 8;
                cp_async16(smem_u32(&sA[s2][row * 72 + v]), Ag + (long)row * p.sA + k0 + v);
                cp_async16(smem_u32(&sB[s2][row * 72 + v]), Bg + (long)row * p.sB + k0 + v);
            }
            asm volatile("cp.async.commit_group;");
            asm volatile("cp.async.wait_group 1;");
        } else {
            asm volatile("cp.async.wait_group 0;");
        }
        __syncthreads();

        const __nv_bfloat16* cA = sA[s];
        const __nv_bfloat16* cB = sB[s];
        #pragma unroll
        for (int kk = 0; kk < 64; kk += 16) {
            uint32_t ar[4][4], br[4][2];
            #pragma unroll
            for (int mi = 0; mi < 4; mi++)
                ldsm_x4(ar[mi], smem_u32(&cA[(wm + mi * 16 + arow) * 72 + kk + ak]));
            #pragma unroll
            for (int np = 0; np < 2; np++) {
                uint32_t rr[4];
                ldsm_x4(rr, smem_u32(&cB[(wn + np * 16 + brow) * 72 + kk + bk]));
                br[2 * np][0] = rr[0]; br[2 * np][1] = rr[1];
                br[2 * np + 1][0] = rr[2]; br[2 * np + 1][1] = rr[3];
            }
            #pragma unroll
            for (int mi = 0; mi < 4; mi++)
                #pragma unroll
                for (int ni = 0; ni < 4; ni++)
                    mma16816(acc[mi][ni], ar[mi], br[ni]);
        }
        __syncthreads();
    }

    #pragma unroll
    for (int mi = 0; mi < 4; mi++)
        #pragma unroll
        for (int ni = 0; ni < 4; ni++) {
            #pragma unroll
            for (int hh = 0; hh < 2; hh++) {
                int r = bm + wm + mi * 16 + g + hh * 8;
                int cc = bn + wn + ni * 8 + 2 * tg;
                float a0 = acc[mi][ni][2 * hh], a1 = acc[mi][ni][2 * hh + 1];
                int bb = r >> 11;
                if (p.epi == 0) {
                    float s0 = expf(p.e0[(long)bb * HID + cc]);
                    float s1 = expf(p.e0[(long)bb * HID + cc + 1]);
                    *(__nv_bfloat162*)&((__nv_bfloat16*)p.C)[offC + (long)r * p.sC + cc] =
                        __floats2bfloat162_rn(a0 * s0, a1 * s1);
                } else if (p.epi == 1) {
                    *(__nv_bfloat162*)&((__nv_bfloat16*)p.C)[offC + (long)r * p.sC + cc] =
                        __floats2bfloat162_rn(a0, a1);
                } else if (p.epi == 3) {
                    float* dst = (float*)p.C + (long)r * p.sC + cc;
                    const float* res = p.e2 + (long)r * DD + cc;
                    dst[0] = res[0] + a0 * p.e0[(long)bb * HID + cc] * p.e1[cc];
                    dst[1] = res[1] + a1 * p.e0[(long)bb * HID + cc + 1] * p.e1[cc + 1];
                } else {   // 5: pair
                    if (cc < 1024) {
                        float s0 = expf(p.e0[(long)bb * HID + cc]);
                        float s1 = expf(p.e0[(long)bb * HID + cc + 1]);
                        *(__nv_bfloat162*)&((__nv_bfloat16*)p.C)[(long)r * DD + cc] =
                            __floats2bfloat162_rn(a0 * s0, a1 * s1);
                    } else {
                        *(__nv_bfloat162*)&((__nv_bfloat16*)p.C2)[(long)r * DD + cc - 1024] =
                            __floats2bfloat162_rn(a0, a1);
                    }
                }
            }
        }
}

static cudaStream_t g_s2 = nullptr;
static cudaEvent_t g_evF = nullptr, g_evJ = nullptr;

static inline void init_attrs() {
    static int inited = 0;
    if (!inited) {
        cudaFuncSetAttribute(k_gemmF, cudaFuncAttributeMaxDynamicSharedMemorySize, GF_SMEM);
        cudaFuncSetAttribute(k_chS_red, cudaFuncAttributeMaxDynamicSharedMemorySize, CHR_SMEM);
        cudaStreamCreateWithFlags(&g_s2, cudaStreamNonBlocking);
        cudaEventCreateWithFlags(&g_evF, cudaEventDisableTiming);
        cudaEventCreateWithFlags(&g_evJ, cudaEventDisableTiming);
        inited = 1;
    }
}

static inline void rungemmF(const GemmF& p, int gx, int gy, int gz) {
    k_gemmF<<<dim3(gx, gy, gz), 256, GF_SMEM>>>(p);
}

#define SYMADDR(v, s) do { void* _p = nullptr; cudaGetSymbolAddress(&_p, s); v = (decltype(v))_p; } while (0)

// ------------------------- launch ----------------------------------------------
extern "C" void kernel_launch(void* const* d_in, const int* in_sizes, int n_in,
                              void* d_out, int out_size) {
    const float* x        = (const float*)d_in[0];
    const float* t        = (const float*)d_in[1];
    const float* n1s      = (const float*)d_in[2];
    const float* n1b      = (const float*)d_in[3];
    const float* n2s      = (const float*)d_in[4];
    const float* n2b      = (const float*)d_in[5];
    const float* tc_w1    = (const float*)d_in[6];
    const float* tc_b1    = (const float*)d_in[7];
    const float* tc_w2    = (const float*)d_in[8];
    const float* tc_b2    = (const float*)d_in[9];
    const float* tc_wa    = (const float*)d_in[10];
    const float* tc_ba    = (const float*)d_in[11];
    const float* tc_wc    = (const float*)d_in[12];
    const float* tc_bc    = (const float*)d_in[13];
    const float* attn_qk_w = (const float*)d_in[14];
    const float* attn_v_w  = (const float*)d_in[15];
    const float* attn_out_w= (const float*)d_in[16];
    const float* doob_w   = (const float*)d_in[17];
    const float* doob_b   = (const float*)d_in[18];
    const float* ch_qk_w  = (const float*)d_in[19];
    const float* ch_v_w   = (const float*)d_in[20];
    const float* ch_out_w = (const float*)d_in[21];
    const float* tau      = (const float*)d_in[22];
    const float* gamma1   = (const float*)d_in[23];
    const float* gamma2   = (const float*)d_in[24];

    float *emb, *p1, *p2, *p3, *av, *cv, *phi, *xmid;
    __nv_bfloat16 *wbf, *x1, *qkb, *vb, *attnb, *x2, *qkcb, *vcb, *Pcp, *chb;
    SYMADDR(emb, g_emb);   SYMADDR(p1, g_p1);     SYMADDR(p2, g_p2);  SYMADDR(p3, g_p3);
    SYMADDR(av, g_av);     SYMADDR(cv, g_cv);     SYMADDR(wbf, g_wbf);
    SYMADDR(x1, g_x1);     SYMADDR(qkb, g_qk);    SYMADDR(vb, g_v);
    SYMADDR(phi, g_phi);
    SYMADDR(attnb, g_attn);SYMADDR(xmid, g_xmid); SYMADDR(x2, g_x2);
    SYMADDR(qkcb, g_qkc);  SYMADDR(vcb, g_vc);
    SYMADDR(Pcp, g_Pc);    SYMADDR(chb, g_ch);

    init_attrs();
    __nv_bfloat16* wqkv = wbf;
    __nv_bfloat16* wo   = wbf + 2 * 1048576;
    __nv_bfloat16* wcqv = wbf + 3 * 1048576;
    __nv_bfloat16* wco  = wbf + 5 * 1048576;

    // ---- fork: conditioning chain on side stream, weight convert on main -------
    cudaEventRecord(g_evF, 0);
    cudaStreamWaitEvent(g_s2, g_evF, 0);

    k_emb<<<(BB * HID + 255) / 256, 256, 0, g_s2>>>(t, emb);
    k_gemv_part<<<dim3(HID / 256, 64), 256, 0, g_s2>>>(emb, tc_w1, p1);
    k_gemv_step<<<dim3(HID / 256, 64, 1), 256, 0, g_s2>>>(p1, tc_b1, tc_w2, tc_w2, p2);
    k_gemv_step<<<dim3(HID / 256, 64, 2), 256, 0, g_s2>>>(p2, tc_b2, tc_wa, tc_wc, p3);
    k_gemv_red2<<<dim3((2 * HID + 255) / 256, 1, 2), 256, 0, g_s2>>>(p3, tc_ba, tc_bc, av, cv);
    cudaEventRecord(g_evJ, g_s2);

    k_convt<<<dim3(32, 32, 6), dim3(32, 8)>>>(attn_qk_w, attn_v_w, attn_out_w,
                                              ch_qk_w, ch_v_w, ch_out_w, wbf);
    cudaStreamWaitEvent(0, g_evJ, 0);   // join: main waits for conditioning

    // ---- token attention ----
    k_ln_mod<<<BN, 256>>>(x, x1, n1s, n1b, av, doob_w, doob_b, phi);
    {   // fused: qk = (x1@Wqk)*exp(a_lg) | v = x1@Wv
        GemmF p = {};
        p.A = x1; p.sA = DD; p.B = wqkv; p.sB = DD; p.K = DD;
        p.C = qkb; p.C2 = vb; p.sC = DD;
        p.epi = 5; p.e0 = av + 3072;
        rungemmF(p, 16, 32, 1);
    }
    k_flash<<<dim3(1, 16, BB * HH), 256>>>(qkb, vb, phi, attnb);
    {   // x_mid = x + (attn @ Wo) * a_gate * gamma1
        GemmF p = {};
        p.A = attnb; p.sA = DD; p.B = wo; p.sB = DD; p.K = DD;
        p.C = xmid; p.sC = DD;
        p.epi = 3; p.e0 = av + 2048; p.e1 = gamma1; p.e2 = x;
        rungemmF(p, 8, 32, 1);
    }

    // ---- channel attention ----
    k_ln_mod<<<BN, 256>>>(xmid, x2, n2s, n2b, cv, nullptr, nullptr, nullptr);
    {   // fused: qkc | vc
        GemmF p = {};
        p.A = x2; p.sA = DD; p.B = wcqv; p.sB = DD; p.K = DD;
        p.C = qkcb; p.C2 = vcb; p.sC = DD;
        p.epi = 5; p.e0 = cv + 3072;
        rungemmF(p, 16, 32, 1);
    }
    k_chS_part<<<dim3(BB * HCC, 4), 256>>>(qkcb, p3);
    k_chS_red<<<BB * HCC, 256, CHR_SMEM>>>(p3, tau, Pcp);
    {   // ch[n][c] = sum_d Vc[n][d] * P[c][d]   (batched z = b*8+hc)
        GemmF p = {};
        p.A = vcb; p.sA = DD; p.B = Pcp; p.sB = 128; p.bBz = 128 * 128; p.K = 128;
        p.C = chb; p.sC = DD;
        p.epi = 1; p.zmode = 1;
        rungemmF(p, 1, 16, BB * HCC);
    }
    {   // out = x_mid + (ch @ Wco) * c_gate * gamma2
        GemmF p = {};
        p.A = chb; p.sA = DD; p.B = wco; p.sB = DD; p.K = DD;
        p.C = d_out; p.sC = DD;
        p.epi = 3; p.e0 = cv + 2048; p.e1 = gamma2; p.e2 = xmid;
        rungemmF(p, 8, 32, 1);
    }
}

// round 15
// speedup vs baseline: 1.0121x; 1.0121x over previous
#include <cuda_runtime.h>
#include <cuda_bf16.h>
#include <math.h>
#include <stdint.h>

#define BB 2
#define NN 2048
#define DD 1024
#define HH 16
#define HCC 8
#define HID 4096
#define BN (BB*NN)

// ------------------------- scratch ----------------------------------------------
__device__ float g_emb[BB*HID];
__device__ float g_p1[64*2*HID];
__device__ float g_p2[64*2*HID];
__device__ float g_p3[2*64*2*HID];             // also reused as chS split-K partials
__device__ float g_av[BB*HID];
__device__ float g_cv[BB*HID];
__device__ __nv_bfloat16 g_wbf[6u*1048576u];   // transposed bf16 weights [n][k]
__device__ __nv_bfloat16 g_x1[BN*DD];
__device__ __nv_bfloat16 g_qk[BN*DD];
__device__ __nv_bfloat16 g_v[BN*DD];
__device__ float g_phi[BB*NN];
__device__ __nv_bfloat16 g_attn[BN*DD];
__device__ float g_xmid[BN*DD];
__device__ __nv_bfloat16 g_x2[BN*DD];
__device__ __nv_bfloat16 g_qkc[BN*DD];
__device__ __nv_bfloat16 g_vc[BN*DD];
__device__ __nv_bfloat16 g_Pc[BB*HCC*128*128];
__device__ __nv_bfloat16 g_ch[BN*DD];

// ------------------------- helpers ---------------------------------------------
__device__ inline float blockRed(float v, int op) {
    __shared__ float sm[32];
    int lane = threadIdx.x & 31, w = threadIdx.x >> 5;
    #pragma unroll
    for (int o = 16; o; o >>= 1) {
        float t = __shfl_xor_sync(0xffffffffu, v, o);
        v = op ? fmaxf(v, t) : v + t;
    }
    if (lane == 0) sm[w] = v;
    __syncthreads();
    int nw = blockDim.x >> 5;
    if (w == 0) {
        v = (lane < nw) ? sm[lane] : (op ? -INFINITY : 0.f);
        #pragma unroll
        for (int o = 16; o; o >>= 1) {
            float t = __shfl_xor_sync(0xffffffffu, v, o);
            v = op ? fmaxf(v, t) : v + t;
        }
        if (lane == 0) sm[0] = v;
    }
    __syncthreads();
    float r = sm[0];
    __syncthreads();
    return r;
}

__device__ inline void mma16816(float* c, const uint32_t* a, const uint32_t* b) {
    asm volatile(
        "mma.sync.aligned.m16n8k16.row.col.f32.bf16.bf16.f32 "
        "{%0,%1,%2,%3}, {%4,%5,%6,%7}, {%8,%9}, {%0,%1,%2,%3};\n"
        : "+f"(c[0]), "+f"(c[1]), "+f"(c[2]), "+f"(c[3])
        : "r"(a[0]), "r"(a[1]), "r"(a[2]), "r"(a[3]), "r"(b[0]), "r"(b[1]));
}

__device__ inline void ldsm_x4(uint32_t* r, uint32_t saddr) {
    asm volatile("ldmatrix.sync.aligned.m8n8.x4.shared.b16 {%0,%1,%2,%3}, [%4];"
        : "=r"(r[0]), "=r"(r[1]), "=r"(r[2]), "=r"(r[3]) : "r"(saddr));
}

__device__ inline void ldsm_x4_t(uint32_t* r, uint32_t saddr) {
    asm volatile("ldmatrix.sync.aligned.m8n8.x4.trans.shared.b16 {%0,%1,%2,%3}, [%4];"
        : "=r"(r[0]), "=r"(r[1]), "=r"(r[2]), "=r"(r[3]) : "r"(saddr));
}

__device__ inline uint32_t packbf(float a, float b) {
    __nv_bfloat162 t = __floats2bfloat162_rn(a, b);
    return *(uint32_t*)&t;
}

__device__ inline uint32_t smem_u32(const void* p) {
    uint32_t a;
    asm("{ .reg .u64 t; cvta.to.shared.u64 t, %1; cvt.u32.u64 %0, t; }" : "=r"(a) : "l"(p));
    return a;
}

__device__ inline void cp_async16(uint32_t saddr, const void* gaddr) {
    asm volatile("cp.async.cg.shared.global [%0], [%1], 16;" :: "r"(saddr), "l"(gaddr));
}

// ------------------------- small kernels ----------------------------------------
__global__ void k_emb(const float* __restrict__ t, float* __restrict__ emb) {
    int i = blockIdx.x * 256 + threadIdx.x;
    if (i >= BB * HID) return;
    int b = i / HID, j = i % HID;
    int jj = j & 2047;
    float f = expf(-9.210340371976184f * (float)jj / 2048.0f);
    float a = t[b] * f;
    emb[i] = (j < 2048) ? cosf(a) : sinf(a);
}

// split-K GEMV partials: 64 k-slices of 64, scalar coalesced loads (R8 exact)
__global__ void k_gemv_part(const float* __restrict__ in, const float* __restrict__ W,
                            float* __restrict__ part) {
    int col = blockIdx.x * 256 + threadIdx.x;
    int k0 = blockIdx.y * 64;
    float a0 = 0.f, a1 = 0.f;
    #pragma unroll 8
    for (int k = k0; k < k0 + 64; k++) {
        float w = W[(long)k * HID + col];
        a0 += in[k] * w;
        a1 += in[HID + k] * w;
    }
    part[((long)blockIdx.y * 2 + 0) * HID + col] = a0;
    part[((long)blockIdx.y * 2 + 1) * HID + col] = a1;
}

// fused: reduce prev partials (+bias, silu), then partial GEMV (R8 exact)
__global__ void k_gemv_step(const float* __restrict__ prevPart,
                            const float* __restrict__ prevBias,
                            const float* __restrict__ W0, const float* __restrict__ W1,
                            float* __restrict__ outPart) {
    __shared__ float in_s[2][64];
    const float* W = blockIdx.z ? W1 : W0;
    float* op = outPart + (long)blockIdx.z * 64 * 2 * HID;
    int tid = threadIdx.x;
    int k0 = blockIdx.y * 64;
    if (tid < 128) {
        int b = tid >> 6, kk = tid & 63, k = k0 + kk;
        float s = prevBias[k];
        #pragma unroll 8
        for (int p2 = 0; p2 < 64; p2++) s += prevPart[((long)p2 * 2 + b) * HID + k];
        in_s[b][kk] = s / (1.f + __expf(-s));
    }
    __syncthreads();
    int col = blockIdx.x * 256 + tid;
    float a0 = 0.f, a1 = 0.f;
    #pragma unroll 8
    for (int kk = 0; kk < 64; kk++) {
        float w = W[(long)(k0 + kk) * HID + col];
        a0 += in_s[0][kk] * w;
        a1 += in_s[1][kk] * w;
    }
    op[((long)blockIdx.y * 2 + 0) * HID + col] = a0;
    op[((long)blockIdx.y * 2 + 1) * HID + col] = a1;
}

__global__ void k_gemv_red2(const float* __restrict__ part, const float* __restrict__ b0,
                            const float* __restrict__ b1, float* __restrict__ o0,
                            float* __restrict__ o1) {
    int i = blockIdx.x * 256 + threadIdx.x;
    if (i >= 2 * HID) return;
    const float* pp = part + (long)blockIdx.z * 64 * 2 * HID;
    const float* bias = blockIdx.z ? b1 : b0;
    float* out = blockIdx.z ? o1 : o0;
    int b = i / HID, col = i % HID;
    float s = bias[col];
    #pragma unroll 8
    for (int p = 0; p < 64; p++) s += pp[((long)p * 2 + b) * HID + col];
    out[(long)b * HID + col] = s;
}

// tiled transpose + fp32->bf16
__global__ void k_convt(const float* __restrict__ w0, const float* __restrict__ w1,
                        const float* __restrict__ w2, const float* __restrict__ w3,
                        const float* __restrict__ w4, const float* __restrict__ w5,
                        __nv_bfloat16* __restrict__ out) {
    __shared__ float t[32][33];
    const float* s = w0;
    int z = blockIdx.z;
    if (z == 1) s = w1; else if (z == 2) s = w2; else if (z == 3) s = w3;
    else if (z == 4) s = w4; else if (z == 5) s = w5;
    int x = blockIdx.x * 32 + threadIdx.x;
    int y0 = blockIdx.y * 32;
    #pragma unroll
    for (int j = 0; j < 32; j += 8)
        t[threadIdx.y + j][threadIdx.x] = s[(long)(y0 + threadIdx.y + j) * DD + x];
    __syncthreads();
    __nv_bfloat16* d = out + (long)z * 1048576;
    int n = blockIdx.x * 32 + threadIdx.y;
    int k = y0 + threadIdx.x;
    #pragma unroll
    for (int j = 0; j < 32; j += 8)
        d[(long)(n + j) * DD + k] = __float2bfloat16(t[threadIdx.x][threadIdx.y + j]);
}

// LayerNorm + modulate -> bf16, optional fused phi (doob) reduction
__global__ void k_ln_mod(const float* __restrict__ xin, __nv_bfloat16* __restrict__ xout,
                         const float* __restrict__ sc, const float* __restrict__ bi,
                         const float* __restrict__ mod, const float* __restrict__ dw,
                         const float* __restrict__ db, float* __restrict__ phi) {
    int r = blockIdx.x;
    int b = r >> 11;
    const float* xr = xin + (long)r * DD;
    int tid = threadIdx.x;
    float v[4];
    float s = 0.f;
    #pragma unroll
    for (int i = 0; i < 4; i++) { v[i] = xr[tid + i * 256]; s += v[i]; }
    s = blockRed(s, 0);
    float mu = s * (1.0f / DD);
    float vs = 0.f;
    #pragma unroll
    for (int i = 0; i < 4; i++) { float d = v[i] - mu; vs += d * d; }
    vs = blockRed(vs, 0);
    float rstd = rsqrtf(vs * (1.0f / DD) + 1e-6f);
    float ps = 0.f;
    #pragma unroll
    for (int i = 0; i < 4; i++) {
        int j = tid + i * 256;
        float y = (v[i] - mu) * rstd * sc[j] + bi[j];
        float m = y * (1.f + mod[(long)b * HID + 1024 + j]) + mod[(long)b * HID + j];
        xout[(long)r * DD + j] = __float2bfloat16(m);
        if (dw) ps += m * dw[j];
    }
    if (dw) {
        ps = blockRed(ps, 0);
        if (tid == 0) phi[r] = ps + db[0];
    }
}

// ------------------------- channel S: split-K Gram partials ----------------------
__global__ void __launch_bounds__(256) k_chS_part(
    const __nv_bfloat16* __restrict__ qkc, float* __restrict__ Spart)
{
    __shared__ __nv_bfloat16 sQt[128 * 72];
    int z = blockIdx.x, sl = blockIdx.y;
    int b = z >> 3, hc = z & 7;
    int tid = threadIdx.x, wid = tid >> 5, lane = tid & 31;
    int g = lane >> 2, tg = lane & 3;
    int wm = (wid & 1) * 64, wn = (wid >> 1) * 32;
    const __nv_bfloat16* base = qkc + ((long)b * NN + sl * 512) * DD + hc * 128;

    int arow = lane & 15, ak = (lane & 16) ? 8 : 0;
    int brow = (lane & 7) + ((lane & 16) ? 8 : 0), bk = (lane & 8) ? 8 : 0;

    float acc[4][4][4];
    #pragma unroll
    for (int i = 0; i < 4; i++)
        #pragma unroll
        for (int j = 0; j < 4; j++)
            #pragma unroll
            for (int q = 0; q < 4; q++) acc[i][j][q] = 0.f;

    uint4 rq[4];
    #pragma unroll
    for (int t = 0; t < 4; t++) {
        int idx = tid + t * 256;
        int tok = idx >> 4, dg = (idx & 15) * 8;
        rq[t] = *(const uint4*)(base + (long)tok * DD + dg);
    }

    for (int ch = 0; ch < 8; ch++) {
        #pragma unroll
        for (int t = 0; t < 4; t++) {
            int idx = tid + t * 256;
            int tok = idx >> 4, dg = (idx & 15) * 8;
            union { uint4 u; __nv_bfloat16 hh[8]; } tv;
            tv.u = rq[t];
            #pragma unroll
            for (int j = 0; j < 8; j++) sQt[(dg + j) * 72 + tok] = tv.hh[j];
        }
        __syncthreads();
        if (ch < 7) {
            #pragma unroll
            for (int t = 0; t < 4; t++) {
                int idx = tid + t * 256;
                int tok = idx >> 4, dg = (idx & 15) * 8;
                rq[t] = *(const uint4*)(base + (long)((ch + 1) * 64 + tok) * DD + dg);
            }
        }
        #pragma unroll
        for (int kk = 0; kk < 64; kk += 16) {
            uint32_t ar[4][4], br[4][2];
            #pragma unroll
            for (int mi = 0; mi < 4; mi++)
                ldsm_x4(ar[mi], smem_u32(&sQt[(wm + mi * 16 + arow) * 72 + kk + ak]));
            #pragma unroll
            for (int np = 0; np < 2; np++) {
                uint32_t rr[4];
                ldsm_x4(rr, smem_u32(&sQt[(wn + np * 16 + brow) * 72 + kk + bk]));
                br[2 * np][0] = rr[0]; br[2 * np][1] = rr[1];
                br[2 * np + 1][0] = rr[2]; br[2 * np + 1][1] = rr[3];
            }
            #pragma unroll
            for (int mi = 0; mi < 4; mi++)
                #pragma unroll
                for (int ni = 0; ni < 4; ni++)
                    mma16816(acc[mi][ni], ar[mi], br[ni]);
        }
        __syncthreads();
    }

    float* dst = Spart + ((long)z * 4 + sl) * 16384;
    #pragma unroll
    for (int mi = 0; mi < 4; mi++)
        #pragma unroll
        for (int ni = 0; ni < 4; ni++) {
            int r0 = wm + mi * 16 + g, c0 = wn + ni * 8 + 2 * tg;
            dst[r0 * 128 + c0] = acc[mi][ni][0];
            dst[r0 * 128 + c0 + 1] = acc[mi][ni][1];
            dst[(r0 + 8) * 128 + c0] = acc[mi][ni][2];
            dst[(r0 + 8) * 128 + c0 + 1] = acc[mi][ni][3];
        }
}

// combine partials + diag-q2 + softmax -> Pc (grid 16)
#define CHR_SMEM (128*129*4 + 512)
__global__ void __launch_bounds__(256) k_chS_red(
    const float* __restrict__ Spart, const float* __restrict__ tau,
    __nv_bfloat16* __restrict__ Pc)
{
    extern __shared__ __align__(16) char smraw[];
    float* sS = (float*)smraw;
    float* sq2 = (float*)(smraw + 128 * 129 * 4);
    int z = blockIdx.x;
    int hc = z & 7;
    int tid = threadIdx.x, wid = tid >> 5, lane = tid & 31;
    float ft = 0.022097086912079608f * tau[hc];
    const float* src = Spart + (long)z * 4 * 16384;

    for (int idx = tid; idx < 16384; idx += 256) {
        float s = src[idx] + src[16384 + idx] + src[2 * 16384 + idx] + src[3 * 16384 + idx];
        sS[(idx >> 7) * 129 + (idx & 127)] = s;
    }
    __syncthreads();
    if (tid < 128) sq2[tid] = sS[tid * 129 + tid];
    __syncthreads();

    for (int it = 0; it < 16; it++) {
        int r = it * 8 + wid;
        float v[4], mx = -1e30f;
        #pragma unroll
        for (int j = 0; j < 4; j++) {
            int c = lane + 32 * j;
            v[j] = (2.f * sS[r * 129 + c] - sq2[c]) * ft;
            mx = fmaxf(mx, v[j]);
        }
        #pragma unroll
        for (int o = 16; o; o >>= 1) mx = fmaxf(mx, __shfl_xor_sync(0xffffffffu, mx, o));
        float sum = 0.f;
        #pragma unroll
        for (int j = 0; j < 4; j++) { v[j] = __expf(v[j] - mx); sum += v[j]; }
        #pragma unroll
        for (int o = 16; o; o >>= 1) sum += __shfl_xor_sync(0xffffffffu, sum, o);
        float inv = 1.f / sum;
        #pragma unroll
        for (int j = 0; j < 4; j++)
            Pc[(long)z * 16384 + r * 128 + lane + 32 * j] = __float2bfloat16(v[j] * inv);
    }
}

// ------------------------- flash token attention ---------------------------------
// R13 structure; bias fused from prefetch registers (no extra sync):
// sBias[n] = phi[b,n] - |k_n|^2, |k_n|^2 reduced over 8 consecutive threads' rk[t]
__global__ void __launch_bounds__(256) k_flash(
    const __nv_bfloat16* __restrict__ qk,
    const __nv_bfloat16* __restrict__ v,
    const float* __restrict__ phi,
    __nv_bfloat16* __restrict__ out)
{
    int z = blockIdx.z;
    int b = z >> 4, h = z & 15;
    const __nv_bfloat16* Qb = qk + ((long)b * NN) * DD + h * 64;
    const __nv_bfloat16* Vb = v  + ((long)b * NN) * DD + h * 64;
    const float* phib = phi + (long)b * NN;
    int m0 = blockIdx.y * 128;

    __shared__ __nv_bfloat16 sK[128][72];
    __shared__ __nv_bfloat16 sVn[128][72];
    __shared__ float sBias[128];

    int tid = threadIdx.x, wid = tid >> 5, lane = tid & 31;
    int g = lane >> 2, tg = lane & 3;
    int mrow = m0 + wid * 16;

    int brow = (lane & 7) + ((lane & 16) ? 8 : 0), bk = (lane & 8) ? 8 : 0;
    int vrow = (lane & 7) + ((lane & 8) ? 8 : 0), vcol = (lane & 16) ? 8 : 0;

    uint32_t qf[4][4];
    #pragma unroll
    for (int kp = 0; kp < 4; kp++) {
        const __nv_bfloat16* q0 = Qb + (long)(mrow + g) * DD + kp * 16 + 2 * tg;
        const __nv_bfloat16* q1 = Qb + (long)(mrow + g + 8) * DD + kp * 16 + 2 * tg;
        qf[kp][0] = *(const uint32_t*)q0;
        qf[kp][1] = *(const uint32_t*)q1;
        qf[kp][2] = *(const uint32_t*)(q0 + 8);
        qf[kp][3] = *(const uint32_t*)(q1 + 8);
    }

    uint4 rk[4], rv[4];
    #pragma unroll
    for (int t = 0; t < 4; t++) {
        int i = tid + t * 256;
        int tok = i >> 3, dv = (i & 7) * 8;
        rk[t] = *(const uint4*)(Qb + (long)tok * DD + dv);
        rv[t] = *(const uint4*)(Vb + (long)tok * DD + dv);
    }

    float m_run[2] = {-1e30f, -1e30f};
    float l_run[2] = {0.f, 0.f};
    float o[8][4];
    #pragma unroll
    for (int i = 0; i < 8; i++)
        #pragma unroll
        for (int j = 0; j < 4; j++) o[i][j] = 0.f;

    for (int n0 = 0; n0 < NN; n0 += 128) {
        // store tile + per-segment q2 partials
        float q2p[4];
        #pragma unroll
        for (int t = 0; t < 4; t++) {
            int i = tid + t * 256;
            int tok = i >> 3, dv = (i & 7) * 8;
            *(uint4*)&sK[tok][dv] = rk[t];
            *(uint4*)&sVn[tok][dv] = rv[t];
            union { uint4 u; __nv_bfloat16 hh[8]; } tv;
            tv.u = rk[t];
            float s = 0.f;
            #pragma unroll
            for (int j = 0; j < 8; j++) {
                float f = __bfloat162float(tv.hh[j]);
                s += f * f;
            }
            q2p[t] = s;
        }
        // reduce over the 8-lane group holding one row
        #pragma unroll
        for (int t = 0; t < 4; t++) {
            q2p[t] += __shfl_xor_sync(0xffffffffu, q2p[t], 1);
            q2p[t] += __shfl_xor_sync(0xffffffffu, q2p[t], 2);
            q2p[t] += __shfl_xor_sync(0xffffffffu, q2p[t], 4);
        }
        if ((tid & 7) == 0) {
            #pragma unroll
            for (int t = 0; t < 4; t++) {
                int row = t * 32 + (tid >> 3);
                sBias[row] = phib[n0 + row] - q2p[t];
            }
        }
        __syncthreads();

        if (n0 + 128 < NN) {
            #pragma unroll
            for (int t = 0; t < 4; t++) {
                int i = tid + t * 256;
                int tok = i >> 3, dv = (i & 7) * 8;
                rk[t] = *(const uint4*)(Qb + (long)(n0 + 128 + tok) * DD + dv);
                rv[t] = *(const uint4*)(Vb + (long)(n0 + 128 + tok) * DD + dv);
            }
        }

        float s[16][4];
        #pragma unroll
        for (int ni = 0; ni < 16; ni++)
            s[ni][0] = s[ni][1] = s[ni][2] = s[ni][3] = 0.f;
        #pragma unroll
        for (int kp = 0; kp < 4; kp++) {
            #pragma unroll
            for (int np = 0; np < 8; np++) {
                uint32_t rr[4];
                ldsm_x4(rr, smem_u32(&sK[np * 16 + brow][kp * 16 + bk]));
                uint32_t b0[2] = { rr[0], rr[1] }, b1[2] = { rr[2], rr[3] };
                mma16816(s[2 * np], qf[kp], b0);
                mma16816(s[2 * np + 1], qf[kp], b1);
            }
        }

        float mx[2] = {-1e30f, -1e30f};
        #pragma unroll
        for (int ni = 0; ni < 16; ni++) {
            #pragma unroll
            for (int j = 0; j < 4; j++) {
                float bval = sBias[ni * 8 + 2 * tg + (j & 1)];
                s[ni][j] = 2.f * s[ni][j] + bval;
                mx[j >> 1] = fmaxf(mx[j >> 1], s[ni][j]);
            }
        }
        #pragma unroll
        for (int r = 0; r < 2; r++) {
            mx[r] = fmaxf(mx[r], __shfl_xor_sync(0xffffffffu, mx[r], 1));
            mx[r] = fmaxf(mx[r], __shfl_xor_sync(0xffffffffu, mx[r], 2));
        }
        float m_new[2], alpha[2], rs[2] = {0.f, 0.f};
        #pragma unroll
        for (int r = 0; r < 2; r++) {
            m_new[r] = fmaxf(m_run[r], mx[r]);
            alpha[r] = __expf(m_run[r] - m_new[r]);
            m_run[r] = m_new[r];
        }
        #pragma unroll
        for (int ni = 0; ni < 16; ni++) {
            #pragma unroll
            for (int j = 0; j < 4; j++) {
                float p = __expf(s[ni][j] - m_new[j >> 1]);
                s[ni][j] = p;
                rs[j >> 1] += p;
            }
        }
        #pragma unroll
        for (int r = 0; r < 2; r++) {
            rs[r] += __shfl_xor_sync(0xffffffffu, rs[r], 1);
            rs[r] += __shfl_xor_sync(0xffffffffu, rs[r], 2);
            l_run[r] = l_run[r] * alpha[r] + rs[r];
        }
        #pragma unroll
        for (int di = 0; di < 8; di++) {
            o[di][0] *= alpha[0]; o[di][1] *= alpha[0];
            o[di][2] *= alpha[1]; o[di][3] *= alpha[1];
        }
        uint32_t pf[8][4];
        #pragma unroll
        for (int kp = 0; kp < 8; kp++) {
            pf[kp][0] = packbf(s[2 * kp][0], s[2 * kp][1]);
            pf[kp][1] = packbf(s[2 * kp][2], s[2 * kp][3]);
            pf[kp][2] = packbf(s[2 * kp + 1][0], s[2 * kp + 1][1]);
            pf[kp][3] = packbf(s[2 * kp + 1][2], s[2 * kp + 1][3]);
        }
        #pragma unroll
        for (int kp = 0; kp < 8; kp++) {
            #pragma unroll
            for (int dp = 0; dp < 4; dp++) {
                uint32_t rr[4];
                ldsm_x4_t(rr, smem_u32(&sVn[kp * 16 + vrow][dp * 16 + vcol]));
                uint32_t b0[2] = { rr[0], rr[1] }, b1[2] = { rr[2], rr[3] };
                mma16816(o[2 * dp], pf[kp], b0);
                mma16816(o[2 * dp + 1], pf[kp], b1);
            }
        }
        __syncthreads();
    }

    float inv0 = 1.f / l_run[0], inv1 = 1.f / l_run[1];
    long r0 = (long)(b * NN + mrow + g) * DD + h * 64;
    long r1 = (long)(b * NN + mrow + g + 8) * DD + h * 64;
    #pragma unroll
    for (int di = 0; di < 8; di++) {
        int col = di * 8 + 2 * tg;
        __nv_bfloat162 v0 = __floats2bfloat162_rn(o[di][0] * inv0, o[di][1] * inv0);
        __nv_bfloat162 v1 = __floats2bfloat162_rn(o[di][2] * inv1, o[di][3] * inv1);
        *(__nv_bfloat162*)&out[r0 + col] = v0;
        *(__nv_bfloat162*)&out[r1 + col] = v1;
    }
}

// ------------------------- generalized fast GEMM (cp.async + ldmatrix) ----------
struct GemmF {
    const __nv_bfloat16 *A, *B;
    long sA, sB, sC;
    long bBz;
    int K;
    void *C, *C2;
    int epi;                   // 0 exp bf16, 1 bf16, 3 residual fp32, 5 pair
    int zmode;
    const float *e0, *e1, *e2;
};

#define GF_SMEM (4*128*72*2)

__global__ void __launch_bounds__(256, 2) k_gemmF(GemmF p) {
    extern __shared__ __nv_bfloat16 smdyn[];
    __nv_bfloat16* sA[2] = { smdyn, smdyn + 128 * 72 };
    __nv_bfloat16* sB[2] = { smdyn + 2 * 128 * 72, smdyn + 3 * 128 * 72 };
    int tid = threadIdx.x, wid = tid >> 5, lane = tid & 31;
    int g = lane >> 2, tg = lane & 3;
    int bm = blockIdx.y * 128, bn = blockIdx.x * 128;
    int wm = (wid & 1) * 64, wn = (wid >> 1) * 32;

    int arow = lane & 15, ak = (lane & 16) ? 8 : 0;
    int brow = (lane & 7) + ((lane & 16) ? 8 : 0), bk = (lane & 8) ? 8 : 0;

    long offA = 0, offB = 0, offC = 0;
    if (p.zmode == 1) {
        int z = blockIdx.z, b = z >> 3, hc = z & 7;
        offA = (long)b * NN * DD + hc * 128;
        offB = (long)z * p.bBz;
        offC = offA;
    }
    const __nv_bfloat16* Ag = p.A + offA + (long)bm * p.sA;
    const __nv_bfloat16* Bg = p.B + offB + (long)bn * p.sB;

    float acc[4][4][4];
    #pragma unroll
    for (int i = 0; i < 4; i++)
        #pragma unroll
        for (int j = 0; j < 4; j++)
            #pragma unroll
            for (int q = 0; q < 4; q++) acc[i][j][q] = 0.f;

    #pragma unroll
    for (int t = 0; t < 4; t++) {
        int idx = tid + t * 256;
        int row = idx >> 3, v = (idx & 7) * 8;
        cp_async16(smem_u32(&sA[0][row * 72 + v]), Ag + (long)row * p.sA + v);
        cp_async16(smem_u32(&sB[0][row * 72 + v]), Bg + (long)row * p.sB + v);
    }
    asm volatile("cp.async.commit_group;");

    int nc = p.K >> 6;
    #pragma unroll 1
    for (int c = 0; c < nc; c++) {
        int s = c & 1;
        if (c < nc - 1) {
            int s2 = s ^ 1, k0 = (c + 1) * 64;
            #pragma unroll
            for (int t = 0; t < 4; t++) {
                int idx = tid + t * 256;
                int row = idx >> 3, v = (idx & 7) * 8;
                cp_async16(smem_u32(&sA[s2][row * 72 + v]), Ag + (long)row * p.sA + k0 + v);
                cp_async16(smem_u32(&sB[s2][row * 72 + v]), Bg + (long)row * p.sB + k0 + v);
            }
            asm volatile("cp.async.commit_group;");
            asm volatile("cp.async.wait_group 1;");
        } else {
            asm volatile("cp.async.wait_group 0;");
        }
        __syncthreads();

        const __nv_bfloat16* cA = sA[s];
        const __nv_bfloat16* cB = sB[s];
        #pragma unroll
        for (int kk = 0; kk < 64; kk += 16) {
            uint32_t ar[4][4], br[4][2];
            #pragma unroll
            for (int mi = 0; mi < 4; mi++)
                ldsm_x4(ar[mi], smem_u32(&cA[(wm + mi * 16 + arow) * 72 + kk + ak]));
            #pragma unroll
            for (int np = 0; np < 2; np++) {
                uint32_t rr[4];
                ldsm_x4(rr, smem_u32(&cB[(wn + np * 16 + brow) * 72 + kk + bk]));
                br[2 * np][0] = rr[0]; br[2 * np][1] = rr[1];
                br[2 * np + 1][0] = rr[2]; br[2 * np + 1][1] = rr[3];
            }
            #pragma unroll
            for (int mi = 0; mi < 4; mi++)
                #pragma unroll
                for (int ni = 0; ni < 4; ni++)
                    mma16816(acc[mi][ni], ar[mi], br[ni]);
        }
        __syncthreads();
    }

    #pragma unroll
    for (int mi = 0; mi < 4; mi++)
        #pragma unroll
        for (int ni = 0; ni < 4; ni++) {
            #pragma unroll
            for (int hh = 0; hh < 2; hh++) {
                int r = bm + wm + mi * 16 + g + hh * 8;
                int cc = bn + wn + ni * 8 + 2 * tg;
                float a0 = acc[mi][ni][2 * hh], a1 = acc[mi][ni][2 * hh + 1];
                int bb = r >> 11;
                if (p.epi == 0) {
                    float s0 = expf(p.e0[(long)bb * HID + cc]);
                    float s1 = expf(p.e0[(long)bb * HID + cc + 1]);
                    *(__nv_bfloat162*)&((__nv_bfloat16*)p.C)[offC + (long)r * p.sC + cc] =
                        __floats2bfloat162_rn(a0 * s0, a1 * s1);
                } else if (p.epi == 1) {
                    *(__nv_bfloat162*)&((__nv_bfloat16*)p.C)[offC + (long)r * p.sC + cc] =
                        __floats2bfloat162_rn(a0, a1);
                } else if (p.epi == 3) {
                    float* dst = (float*)p.C + (long)r * p.sC + cc;
                    const float* res = p.e2 + (long)r * DD + cc;
                    dst[0] = res[0] + a0 * p.e0[(long)bb * HID + cc] * p.e1[cc];
                    dst[1] = res[1] + a1 * p.e0[(long)bb * HID + cc + 1] * p.e1[cc + 1];
                } else {   // 5: pair
                    if (cc < 1024) {
                        float s0 = expf(p.e0[(long)bb * HID + cc]);
                        float s1 = expf(p.e0[(long)bb * HID + cc + 1]);
                        *(__nv_bfloat162*)&((__nv_bfloat16*)p.C)[(long)r * DD + cc] =
                            __floats2bfloat162_rn(a0 * s0, a1 * s1);
                    } else {
                        *(__nv_bfloat162*)&((__nv_bfloat16*)p.C2)[(long)r * DD + cc - 1024] =
                            __floats2bfloat162_rn(a0, a1);
                    }
                }
            }
        }
}

static cudaStream_t g_s2 = nullptr;
static cudaEvent_t g_evF = nullptr, g_evJ = nullptr;

static inline void init_attrs() {
    static int inited = 0;
    if (!inited) {
        cudaFuncSetAttribute(k_gemmF, cudaFuncAttributeMaxDynamicSharedMemorySize, GF_SMEM);
        cudaFuncSetAttribute(k_chS_red, cudaFuncAttributeMaxDynamicSharedMemorySize, CHR_SMEM);
        cudaStreamCreateWithFlags(&g_s2, cudaStreamNonBlocking);
        cudaEventCreateWithFlags(&g_evF, cudaEventDisableTiming);
        cudaEventCreateWithFlags(&g_evJ, cudaEventDisableTiming);
        inited = 1;
    }
}

static inline void rungemmF(const GemmF& p, int gx, int gy, int gz) {
    k_gemmF<<<dim3(gx, gy, gz), 256, GF_SMEM>>>(p);
}

#define SYMADDR(v, s) do { void* _p = nullptr; cudaGetSymbolAddress(&_p, s); v = (decltype(v))_p; } while (0)

// ------------------------- launch ----------------------------------------------
extern "C" void kernel_launch(void* const* d_in, const int* in_sizes, int n_in,
                              void* d_out, int out_size) {
    const float* x        = (const float*)d_in[0];
    const float* t        = (const float*)d_in[1];
    const float* n1s      = (const float*)d_in[2];
    const float* n1b      = (const float*)d_in[3];
    const float* n2s      = (const float*)d_in[4];
    const float* n2b      = (const float*)d_in[5];
    const float* tc_w1    = (const float*)d_in[6];
    const float* tc_b1    = (const float*)d_in[7];
    const float* tc_w2    = (const float*)d_in[8];
    const float* tc_b2    = (const float*)d_in[9];
    const float* tc_wa    = (const float*)d_in[10];
    const float* tc_ba    = (const float*)d_in[11];
    const float* tc_wc    = (const float*)d_in[12];
    const float* tc_bc    = (const float*)d_in[13];
    const float* attn_qk_w = (const float*)d_in[14];
    const float* attn_v_w  = (const float*)d_in[15];
    const float* attn_out_w= (const float*)d_in[16];
    const float* doob_w   = (const float*)d_in[17];
    const float* doob_b   = (const float*)d_in[18];
    const float* ch_qk_w  = (const float*)d_in[19];
    const float* ch_v_w   = (const float*)d_in[20];
    const float* ch_out_w = (const float*)d_in[21];
    const float* tau      = (const float*)d_in[22];
    const float* gamma1   = (const float*)d_in[23];
    const float* gamma2   = (const float*)d_in[24];

    float *emb, *p1, *p2, *p3, *av, *cv, *phi, *xmid;
    __nv_bfloat16 *wbf, *x1, *qkb, *vb, *attnb, *x2, *qkcb, *vcb, *Pcp, *chb;
    SYMADDR(emb, g_emb);   SYMADDR(p1, g_p1);     SYMADDR(p2, g_p2);  SYMADDR(p3, g_p3);
    SYMADDR(av, g_av);     SYMADDR(cv, g_cv);     SYMADDR(wbf, g_wbf);
    SYMADDR(x1, g_x1);     SYMADDR(qkb, g_qk);    SYMADDR(vb, g_v);
    SYMADDR(phi, g_phi);
    SYMADDR(attnb, g_attn);SYMADDR(xmid, g_xmid); SYMADDR(x2, g_x2);
    SYMADDR(qkcb, g_qkc);  SYMADDR(vcb, g_vc);
    SYMADDR(Pcp, g_Pc);    SYMADDR(chb, g_ch);

    init_attrs();
    __nv_bfloat16* wqkv = wbf;
    __nv_bfloat16* wo   = wbf + 2 * 1048576;
    __nv_bfloat16* wcqv = wbf + 3 * 1048576;
    __nv_bfloat16* wco  = wbf + 5 * 1048576;

    // ---- fork: conditioning chain on side stream, weight convert on main -------
    cudaEventRecord(g_evF, 0);
    cudaStreamWaitEvent(g_s2, g_evF, 0);

    k_emb<<<(BB * HID + 255) / 256, 256, 0, g_s2>>>(t, emb);
    k_gemv_part<<<dim3(HID / 256, 64), 256, 0, g_s2>>>(emb, tc_w1, p1);
    k_gemv_step<<<dim3(HID / 256, 64, 1), 256, 0, g_s2>>>(p1, tc_b1, tc_w2, tc_w2, p2);
    k_gemv_step<<<dim3(HID / 256, 64, 2), 256, 0, g_s2>>>(p2, tc_b2, tc_wa, tc_wc, p3);
    k_gemv_red2<<<dim3((2 * HID + 255) / 256, 1, 2), 256, 0, g_s2>>>(p3, tc_ba, tc_bc, av, cv);
    cudaEventRecord(g_evJ, g_s2);

    k_convt<<<dim3(32, 32, 6), dim3(32, 8)>>>(attn_qk_w, attn_v_w, attn_out_w,
                                              ch_qk_w, ch_v_w, ch_out_w, wbf);
    cudaStreamWaitEvent(0, g_evJ, 0);   // join: main waits for conditioning

    // ---- token attention ----
    k_ln_mod<<<BN, 256>>>(x, x1, n1s, n1b, av, doob_w, doob_b, phi);
    {   // fused: qk = (x1@Wqk)*exp(a_lg) | v = x1@Wv
        GemmF p = {};
        p.A = x1; p.sA = DD; p.B = wqkv; p.sB = DD; p.K = DD;
        p.C = qkb; p.C2 = vb; p.sC = DD;
        p.epi = 5; p.e0 = av + 3072;
        rungemmF(p, 16, 32, 1);
    }
    k_flash<<<dim3(1, 16, BB * HH), 256>>>(qkb, vb, phi, attnb);
    {   // x_mid = x + (attn @ Wo) * a_gate * gamma1
        GemmF p = {};
        p.A = attnb; p.sA = DD; p.B = wo; p.sB = DD; p.K = DD;
        p.C = xmid; p.sC = DD;
        p.epi = 3; p.e0 = av + 2048; p.e1 = gamma1; p.e2 = x;
        rungemmF(p, 8, 32, 1);
    }

    // ---- channel attention ----
    k_ln_mod<<<BN, 256>>>(xmid, x2, n2s, n2b, cv, nullptr, nullptr, nullptr);
    {   // fused: qkc | vc
        GemmF p = {};
        p.A = x2; p.sA = DD; p.B = wcqv; p.sB = DD; p.K = DD;
        p.C = qkcb; p.C2 = vcb; p.sC = DD;
        p.epi = 5; p.e0 = cv + 3072;
        rungemmF(p, 16, 32, 1);
    }
    k_chS_part<<<dim3(BB * HCC, 4), 256>>>(qkcb, p3);
    k_chS_red<<<BB * HCC, 256, CHR_SMEM>>>(p3, tau, Pcp);
    {   // ch[n][c] = sum_d Vc[n][d] * P[c][d]   (batched z = b*8+hc)
        GemmF p = {};
        p.A = vcb; p.sA = DD; p.B = Pcp; p.sB = 128; p.bBz = 128 * 128; p.K = 128;
        p.C = chb; p.sC = DD;
        p.epi = 1; p.zmode = 1;
        rungemmF(p, 1, 16, BB * HCC);
    }
    {   // out = x_mid + (ch @ Wco) * c_gate * gamma2
        GemmF p = {};
        p.A = chb; p.sA = DD; p.B = wco; p.sB = DD; p.K = DD;
        p.C = d_out; p.sC = DD;
        p.epi = 3; p.e0 = cv + 2048; p.e1 = gamma2; p.e2 = xmid;
        rungemmF(p, 8, 32, 1);
    }
}

// round 16
// speedup vs baseline: 1.0350x; 1.0226x over previous
#include <cuda_runtime.h>
#include <cuda_bf16.h>
#include <math.h>
#include <stdint.h>

#define BB 2
#define NN 2048
#define DD 1024
#define HH 16
#define HCC 8
#define HID 4096
#define BN (BB*NN)

// ------------------------- scratch ----------------------------------------------
__device__ float g_emb[BB*HID];
__device__ float g_p1[64*2*HID];
__device__ float g_p2[64*2*HID];
__device__ float g_p3[2*64*2*HID];             // also reused as chS split-K partials
__device__ float g_av[BB*HID];
__device__ float g_cv[BB*HID];
__device__ __nv_bfloat16 g_wbf[6u*1048576u];   // transposed bf16 weights [n][k]
__device__ __nv_bfloat16 g_x1[BN*DD];
__device__ __nv_bfloat16 g_qk[BN*DD];
__device__ __nv_bfloat16 g_v[BN*DD];
__device__ float g_bias[BB*HH*NN];
__device__ float g_phi[BB*NN];
__device__ __nv_bfloat16 g_attn[BN*DD];
__device__ float g_xmid[BN*DD];
__device__ __nv_bfloat16 g_x2[BN*DD];
__device__ __nv_bfloat16 g_qkc[BN*DD];
__device__ __nv_bfloat16 g_vc[BN*DD];
__device__ __nv_bfloat16 g_Pc[BB*HCC*128*128];
__device__ __nv_bfloat16 g_ch[BN*DD];

// ------------------------- helpers ---------------------------------------------
__device__ inline float blockRed(float v, int op) {
    __shared__ float sm[32];
    int lane = threadIdx.x & 31, w = threadIdx.x >> 5;
    #pragma unroll
    for (int o = 16; o; o >>= 1) {
        float t = __shfl_xor_sync(0xffffffffu, v, o);
        v = op ? fmaxf(v, t) : v + t;
    }
    if (lane == 0) sm[w] = v;
    __syncthreads();
    int nw = blockDim.x >> 5;
    if (w == 0) {
        v = (lane < nw) ? sm[lane] : (op ? -INFINITY : 0.f);
        #pragma unroll
        for (int o = 16; o; o >>= 1) {
            float t = __shfl_xor_sync(0xffffffffu, v, o);
            v = op ? fmaxf(v, t) : v + t;
        }
        if (lane == 0) sm[0] = v;
    }
    __syncthreads();
    float r = sm[0];
    __syncthreads();
    return r;
}

__device__ inline void mma16816(float* c, const uint32_t* a, const uint32_t* b) {
    asm volatile(
        "mma.sync.aligned.m16n8k16.row.col.f32.bf16.bf16.f32 "
        "{%0,%1,%2,%3}, {%4,%5,%6,%7}, {%8,%9}, {%0,%1,%2,%3};\n"
        : "+f"(c[0]), "+f"(c[1]), "+f"(c[2]), "+f"(c[3])
        : "r"(a[0]), "r"(a[1]), "r"(a[2]), "r"(a[3]), "r"(b[0]), "r"(b[1]));
}

__device__ inline void ldsm_x4(uint32_t* r, uint32_t saddr) {
    asm volatile("ldmatrix.sync.aligned.m8n8.x4.shared.b16 {%0,%1,%2,%3}, [%4];"
        : "=r"(r[0]), "=r"(r[1]), "=r"(r[2]), "=r"(r[3]) : "r"(saddr));
}

__device__ inline void ldsm_x4_t(uint32_t* r, uint32_t saddr) {
    asm volatile("ldmatrix.sync.aligned.m8n8.x4.trans.shared.b16 {%0,%1,%2,%3}, [%4];"
        : "=r"(r[0]), "=r"(r[1]), "=r"(r[2]), "=r"(r[3]) : "r"(saddr));
}

__device__ inline uint32_t packbf(float a, float b) {
    __nv_bfloat162 t = __floats2bfloat162_rn(a, b);
    return *(uint32_t*)&t;
}

__device__ inline uint32_t smem_u32(const void* p) {
    uint32_t a;
    asm("{ .reg .u64 t; cvta.to.shared.u64 t, %1; cvt.u32.u64 %0, t; }" : "=r"(a) : "l"(p));
    return a;
}

__device__ inline void cp_async16(uint32_t saddr, const void* gaddr) {
    asm volatile("cp.async.cg.shared.global [%0], [%1], 16;" :: "r"(saddr), "l"(gaddr));
}

// ------------------------- small kernels ----------------------------------------
__global__ void k_emb(const float* __restrict__ t, float* __restrict__ emb) {
    int i = blockIdx.x * 256 + threadIdx.x;
    if (i >= BB * HID) return;
    int b = i / HID, j = i % HID;
    int jj = j & 2047;
    float f = expf(-9.210340371976184f * (float)jj / 2048.0f);
    float a = t[b] * f;
    emb[i] = (j < 2048) ? cosf(a) : sinf(a);
}

// split-K GEMV partials: 64 k-slices of 64, scalar coalesced loads (R8 exact)
__global__ void k_gemv_part(const float* __restrict__ in, const float* __restrict__ W,
                            float* __restrict__ part) {
    int col = blockIdx.x * 256 + threadIdx.x;
    int k0 = blockIdx.y * 64;
    float a0 = 0.f, a1 = 0.f;
    #pragma unroll 8
    for (int k = k0; k < k0 + 64; k++) {
        float w = W[(long)k * HID + col];
        a0 += in[k] * w;
        a1 += in[HID + k] * w;
    }
    part[((long)blockIdx.y * 2 + 0) * HID + col] = a0;
    part[((long)blockIdx.y * 2 + 1) * HID + col] = a1;
}

// fused: reduce prev partials (+bias, silu), then partial GEMV (R8 exact)
__global__ void k_gemv_step(const float* __restrict__ prevPart,
                            const float* __restrict__ prevBias,
                            const float* __restrict__ W0, const float* __restrict__ W1,
                            float* __restrict__ outPart) {
    __shared__ float in_s[2][64];
    const float* W = blockIdx.z ? W1 : W0;
    float* op = outPart + (long)blockIdx.z * 64 * 2 * HID;
    int tid = threadIdx.x;
    int k0 = blockIdx.y * 64;
    if (tid < 128) {
        int b = tid >> 6, kk = tid & 63, k = k0 + kk;
        float s = prevBias[k];
        #pragma unroll 8
        for (int p2 = 0; p2 < 64; p2++) s += prevPart[((long)p2 * 2 + b) * HID + k];
        in_s[b][kk] = s / (1.f + __expf(-s));
    }
    __syncthreads();
    int col = blockIdx.x * 256 + tid;
    float a0 = 0.f, a1 = 0.f;
    #pragma unroll 8
    for (int kk = 0; kk < 64; kk++) {
        float w = W[(long)(k0 + kk) * HID + col];
        a0 += in_s[0][kk] * w;
        a1 += in_s[1][kk] * w;
    }
    op[((long)blockIdx.y * 2 + 0) * HID + col] = a0;
    op[((long)blockIdx.y * 2 + 1) * HID + col] = a1;
}

__global__ void k_gemv_red2(const float* __restrict__ part, const float* __restrict__ b0,
                            const float* __restrict__ b1, float* __restrict__ o0,
                            float* __restrict__ o1) {
    int i = blockIdx.x * 256 + threadIdx.x;
    if (i >= 2 * HID) return;
    const float* pp = part + (long)blockIdx.z * 64 * 2 * HID;
    const float* bias = blockIdx.z ? b1 : b0;
    float* out = blockIdx.z ? o1 : o0;
    int b = i / HID, col = i % HID;
    float s = bias[col];
    #pragma unroll 8
    for (int p = 0; p < 64; p++) s += pp[((long)p * 2 + b) * HID + col];
    out[(long)b * HID + col] = s;
}

// tiled transpose + fp32->bf16
__global__ void k_convt(const float* __restrict__ w0, const float* __restrict__ w1,
                        const float* __restrict__ w2, const float* __restrict__ w3,
                        const float* __restrict__ w4, const float* __restrict__ w5,
                        __nv_bfloat16* __restrict__ out) {
    __shared__ float t[32][33];
    const float* s = w0;
    int z = blockIdx.z;
    if (z == 1) s = w1; else if (z == 2) s = w2; else if (z == 3) s = w3;
    else if (z == 4) s = w4; else if (z == 5) s = w5;
    int x = blockIdx.x * 32 + threadIdx.x;
    int y0 = blockIdx.y * 32;
    #pragma unroll
    for (int j = 0; j < 32; j += 8)
        t[threadIdx.y + j][threadIdx.x] = s[(long)(y0 + threadIdx.y + j) * DD + x];
    __syncthreads();
    __nv_bfloat16* d = out + (long)z * 1048576;
    int n = blockIdx.x * 32 + threadIdx.y;
    int k = y0 + threadIdx.x;
    #pragma unroll
    for (int j = 0; j < 32; j += 8)
        d[(long)(n + j) * DD + k] = __float2bfloat16(t[threadIdx.x][threadIdx.y + j]);
}

// LayerNorm + modulate -> bf16, optional fused phi (doob) reduction
__global__ void k_ln_mod(const float* __restrict__ xin, __nv_bfloat16* __restrict__ xout,
                         const float* __restrict__ sc, const float* __restrict__ bi,
                         const float* __restrict__ mod, const float* __restrict__ dw,
                         const float* __restrict__ db, float* __restrict__ phi) {
    int r = blockIdx.x;
    int b = r >> 11;
    const float* xr = xin + (long)r * DD;
    int tid = threadIdx.x;
    float v[4];
    float s = 0.f;
    #pragma unroll
    for (int i = 0; i < 4; i++) { v[i] = xr[tid + i * 256]; s += v[i]; }
    s = blockRed(s, 0);
    float mu = s * (1.0f / DD);
    float vs = 0.f;
    #pragma unroll
    for (int i = 0; i < 4; i++) { float d = v[i] - mu; vs += d * d; }
    vs = blockRed(vs, 0);
    float rstd = rsqrtf(vs * (1.0f / DD) + 1e-6f);
    float ps = 0.f;
    #pragma unroll
    for (int i = 0; i < 4; i++) {
        int j = tid + i * 256;
        float y = (v[i] - mu) * rstd * sc[j] + bi[j];
        float m = y * (1.f + mod[(long)b * HID + 1024 + j]) + mod[(long)b * HID + j];
        xout[(long)r * DD + j] = __float2bfloat16(m);
        if (dw) ps += m * dw[j];
    }
    if (dw) {
        ps = blockRed(ps, 0);
        if (tid == 0) phi[r] = ps + db[0];
    }
}

// bias[z*NN+n] = phi[b,n] - |q[b,h,n,:]|^2
__global__ void k_bias(const __nv_bfloat16* __restrict__ qk, const float* __restrict__ phi,
                       float* __restrict__ bias) {
    int gid = blockIdx.x * 8 + (threadIdx.x >> 5);
    int lane = threadIdx.x & 31;
    int n = gid & 2047;
    int h = (gid >> 11) & 15;
    int b = gid >> 15;
    const __nv_bfloat16* p = qk + ((long)b * NN + n) * DD + h * 64;
    float f0 = __bfloat162float(p[lane]);
    float f1 = __bfloat162float(p[lane + 32]);
    float s = f0 * f0 + f1 * f1;
    #pragma unroll
    for (int o = 16; o; o >>= 1) s += __shfl_xor_sync(0xffffffffu, s, o);
    if (lane == 0) bias[gid] = phi[b * NN + n] - s;
}

// ------------------------- channel S: split-K Gram partials ----------------------
__global__ void __launch_bounds__(256) k_chS_part(
    const __nv_bfloat16* __restrict__ qkc, float* __restrict__ Spart)
{
    __shared__ __nv_bfloat16 sQt[128 * 72];
    int z = blockIdx.x, sl = blockIdx.y;
    int b = z >> 3, hc = z & 7;
    int tid = threadIdx.x, wid = tid >> 5, lane = tid & 31;
    int g = lane >> 2, tg = lane & 3;
    int wm = (wid & 1) * 64, wn = (wid >> 1) * 32;
    const __nv_bfloat16* base = qkc + ((long)b * NN + sl * 512) * DD + hc * 128;

    int arow = lane & 15, ak = (lane & 16) ? 8 : 0;
    int brow = (lane & 7) + ((lane & 16) ? 8 : 0), bk = (lane & 8) ? 8 : 0;

    float acc[4][4][4];
    #pragma unroll
    for (int i = 0; i < 4; i++)
        #pragma unroll
        for (int j = 0; j < 4; j++)
            #pragma unroll
            for (int q = 0; q < 4; q++) acc[i][j][q] = 0.f;

    uint4 rq[4];
    #pragma unroll
    for (int t = 0; t < 4; t++) {
        int idx = tid + t * 256;
        int tok = idx >> 4, dg = (idx & 15) * 8;
        rq[t] = *(const uint4*)(base + (long)tok * DD + dg);
    }

    for (int ch = 0; ch < 8; ch++) {
        #pragma unroll
        for (int t = 0; t < 4; t++) {
            int idx = tid + t * 256;
            int tok = idx >> 4, dg = (idx & 15) * 8;
            union { uint4 u; __nv_bfloat16 hh[8]; } tv;
            tv.u = rq[t];
            #pragma unroll
            for (int j = 0; j < 8; j++) sQt[(dg + j) * 72 + tok] = tv.hh[j];
        }
        __syncthreads();
        if (ch < 7) {
            #pragma unroll
            for (int t = 0; t < 4; t++) {
                int idx = tid + t * 256;
                int tok = idx >> 4, dg = (idx & 15) * 8;
                rq[t] = *(const uint4*)(base + (long)((ch + 1) * 64 + tok) * DD + dg);
            }
        }
        #pragma unroll
        for (int kk = 0; kk < 64; kk += 16) {
            uint32_t ar[4][4], br[4][2];
            #pragma unroll
            for (int mi = 0; mi < 4; mi++)
                ldsm_x4(ar[mi], smem_u32(&sQt[(wm + mi * 16 + arow) * 72 + kk + ak]));
            #pragma unroll
            for (int np = 0; np < 2; np++) {
                uint32_t rr[4];
                ldsm_x4(rr, smem_u32(&sQt[(wn + np * 16 + brow) * 72 + kk + bk]));
                br[2 * np][0] = rr[0]; br[2 * np][1] = rr[1];
                br[2 * np + 1][0] = rr[2]; br[2 * np + 1][1] = rr[3];
            }
            #pragma unroll
            for (int mi = 0; mi < 4; mi++)
                #pragma unroll
                for (int ni = 0; ni < 4; ni++)
                    mma16816(acc[mi][ni], ar[mi], br[ni]);
        }
        __syncthreads();
    }

    float* dst = Spart + ((long)z * 4 + sl) * 16384;
    #pragma unroll
    for (int mi = 0; mi < 4; mi++)
        #pragma unroll
        for (int ni = 0; ni < 4; ni++) {
            int r0 = wm + mi * 16 + g, c0 = wn + ni * 8 + 2 * tg;
            *(float2*)&dst[r0 * 128 + c0] = make_float2(acc[mi][ni][0], acc[mi][ni][1]);
            *(float2*)&dst[(r0 + 8) * 128 + c0] = make_float2(acc[mi][ni][2], acc[mi][ni][3]);
        }
}

// combine partials + diag-q2 + softmax -> Pc (grid 16)
#define CHR_SMEM (128*129*4 + 512)
__global__ void __launch_bounds__(256) k_chS_red(
    const float* __restrict__ Spart, const float* __restrict__ tau,
    __nv_bfloat16* __restrict__ Pc)
{
    extern __shared__ __align__(16) char smraw[];
    float* sS = (float*)smraw;
    float* sq2 = (float*)(smraw + 128 * 129 * 4);
    int z = blockIdx.x;
    int hc = z & 7;
    int tid = threadIdx.x, wid = tid >> 5, lane = tid & 31;
    float ft = 0.022097086912079608f * tau[hc];
    const float* src = Spart + (long)z * 4 * 16384;

    for (int idx = tid; idx < 16384; idx += 256) {
        float s = src[idx] + src[16384 + idx] + src[2 * 16384 + idx] + src[3 * 16384 + idx];
        sS[(idx >> 7) * 129 + (idx & 127)] = s;
    }
    __syncthreads();
    if (tid < 128) sq2[tid] = sS[tid * 129 + tid];
    __syncthreads();

    for (int it = 0; it < 16; it++) {
        int r = it * 8 + wid;
        float v[4], mx = -1e30f;
        #pragma unroll
        for (int j = 0; j < 4; j++) {
            int c = lane + 32 * j;
            v[j] = (2.f * sS[r * 129 + c] - sq2[c]) * ft;
            mx = fmaxf(mx, v[j]);
        }
        #pragma unroll
        for (int o = 16; o; o >>= 1) mx = fmaxf(mx, __shfl_xor_sync(0xffffffffu, mx, o));
        float sum = 0.f;
        #pragma unroll
        for (int j = 0; j < 4; j++) { v[j] = __expf(v[j] - mx); sum += v[j]; }
        #pragma unroll
        for (int o = 16; o; o >>= 1) sum += __shfl_xor_sync(0xffffffffu, sum, o);
        float inv = 1.f / sum;
        #pragma unroll
        for (int j = 0; j < 4; j++)
            Pc[(long)z * 16384 + r * 128 + lane + 32 * j] = __float2bfloat16(v[j] * inv);
    }
}

// ------------------------- flash token attention (R13 exact) ---------------------
__global__ void __launch_bounds__(256) k_flash(
    const __nv_bfloat16* __restrict__ qk,
    const __nv_bfloat16* __restrict__ v,
    const float* __restrict__ bias,
    __nv_bfloat16* __restrict__ out)
{
    int z = blockIdx.z;
    int b = z >> 4, h = z & 15;
    const __nv_bfloat16* Qb = qk + ((long)b * NN) * DD + h * 64;
    const __nv_bfloat16* Vb = v  + ((long)b * NN) * DD + h * 64;
    const float* biasb = bias + (long)z * NN;
    int m0 = blockIdx.y * 128;

    __shared__ __nv_bfloat16 sK[128][72];
    __shared__ __nv_bfloat16 sVn[128][72];
    __shared__ float sBias[128];

    int tid = threadIdx.x, wid = tid >> 5, lane = tid & 31;
    int g = lane >> 2, tg = lane & 3;
    int mrow = m0 + wid * 16;

    int brow = (lane & 7) + ((lane & 16) ? 8 : 0), bk = (lane & 8) ? 8 : 0;
    int vrow = (lane & 7) + ((lane & 8) ? 8 : 0), vcol = (lane & 16) ? 8 : 0;

    uint32_t qf[4][4];
    #pragma unroll
    for (int kp = 0; kp < 4; kp++) {
        const __nv_bfloat16* q0 = Qb + (long)(mrow + g) * DD + kp * 16 + 2 * tg;
        const __nv_bfloat16* q1 = Qb + (long)(mrow + g + 8) * DD + kp * 16 + 2 * tg;
        qf[kp][0] = *(const uint32_t*)q0;
        qf[kp][1] = *(const uint32_t*)q1;
        qf[kp][2] = *(const uint32_t*)(q0 + 8);
        qf[kp][3] = *(const uint32_t*)(q1 + 8);
    }

    uint4 rk[4], rv[4];
    #pragma unroll
    for (int t = 0; t < 4; t++) {
        int i = tid + t * 256;
        int tok = i >> 3, dv = (i & 7) * 8;
        rk[t] = *(const uint4*)(Qb + (long)tok * DD + dv);
        rv[t] = *(const uint4*)(Vb + (long)tok * DD + dv);
    }

    float m_run[2] = {-1e30f, -1e30f};
    float l_run[2] = {0.f, 0.f};
    float o[8][4];
    #pragma unroll
    for (int i = 0; i < 8; i++)
        #pragma unroll
        for (int j = 0; j < 4; j++) o[i][j] = 0.f;

    for (int n0 = 0; n0 < NN; n0 += 128) {
        #pragma unroll
        for (int t = 0; t < 4; t++) {
            int i = tid + t * 256;
            int tok = i >> 3, dv = (i & 7) * 8;
            *(uint4*)&sK[tok][dv] = rk[t];
            *(uint4*)&sVn[tok][dv] = rv[t];
        }
        if (tid < 128) sBias[tid] = biasb[n0 + tid];
        __syncthreads();

        if (n0 + 128 < NN) {
            #pragma unroll
            for (int t = 0; t < 4; t++) {
                int i = tid + t * 256;
                int tok = i >> 3, dv = (i & 7) * 8;
                rk[t] = *(const uint4*)(Qb + (long)(n0 + 128 + tok) * DD + dv);
                rv[t] = *(const uint4*)(Vb + (long)(n0 + 128 + tok) * DD + dv);
            }
        }

        float s[16][4];
        #pragma unroll
        for (int ni = 0; ni < 16; ni++)
            s[ni][0] = s[ni][1] = s[ni][2] = s[ni][3] = 0.f;
        #pragma unroll
        for (int kp = 0; kp < 4; kp++) {
            #pragma unroll
            for (int np = 0; np < 8; np++) {
                uint32_t rr[4];
                ldsm_x4(rr, smem_u32(&sK[np * 16 + brow][kp * 16 + bk]));
                uint32_t b0[2] = { rr[0], rr[1] }, b1[2] = { rr[2], rr[3] };
                mma16816(s[2 * np], qf[kp], b0);
                mma16816(s[2 * np + 1], qf[kp], b1);
            }
        }

        float mx[2] = {-1e30f, -1e30f};
        #pragma unroll
        for (int ni = 0; ni < 16; ni++) {
            #pragma unroll
            for (int j = 0; j < 4; j++) {
                float bval = sBias[ni * 8 + 2 * tg + (j & 1)];
                s[ni][j] = 2.f * s[ni][j] + bval;
                mx[j >> 1] = fmaxf(mx[j >> 1], s[ni][j]);
            }
        }
        #pragma unroll
        for (int r = 0; r < 2; r++) {
            mx[r] = fmaxf(mx[r], __shfl_xor_sync(0xffffffffu, mx[r], 1));
            mx[r] = fmaxf(mx[r], __shfl_xor_sync(0xffffffffu, mx[r], 2));
        }
        float m_new[2], alpha[2], rs[2] = {0.f, 0.f};
        #pragma unroll
        for (int r = 0; r < 2; r++) {
            m_new[r] = fmaxf(m_run[r], mx[r]);
            alpha[r] = __expf(m_run[r] - m_new[r]);
            m_run[r] = m_new[r];
        }
        #pragma unroll
        for (int ni = 0; ni < 16; ni++) {
            #pragma unroll
            for (int j = 0; j < 4; j++) {
                float p = __expf(s[ni][j] - m_new[j >> 1]);
                s[ni][j] = p;
                rs[j >> 1] += p;
            }
        }
        #pragma unroll
        for (int r = 0; r < 2; r++) {
            rs[r] += __shfl_xor_sync(0xffffffffu, rs[r], 1);
            rs[r] += __shfl_xor_sync(0xffffffffu, rs[r], 2);
            l_run[r] = l_run[r] * alpha[r] + rs[r];
        }
        #pragma unroll
        for (int di = 0; di < 8; di++) {
            o[di][0] *= alpha[0]; o[di][1] *= alpha[0];
            o[di][2] *= alpha[1]; o[di][3] *= alpha[1];
        }
        uint32_t pf[8][4];
        #pragma unroll
        for (int kp = 0; kp < 8; kp++) {
            pf[kp][0] = packbf(s[2 * kp][0], s[2 * kp][1]);
            pf[kp][1] = packbf(s[2 * kp][2], s[2 * kp][3]);
            pf[kp][2] = packbf(s[2 * kp + 1][0], s[2 * kp + 1][1]);
            pf[kp][3] = packbf(s[2 * kp + 1][2], s[2 * kp + 1][3]);
        }
        #pragma unroll
        for (int kp = 0; kp < 8; kp++) {
            #pragma unroll
            for (int dp = 0; dp < 4; dp++) {
                uint32_t rr[4];
                ldsm_x4_t(rr, smem_u32(&sVn[kp * 16 + vrow][dp * 16 + vcol]));
                uint32_t b0[2] = { rr[0], rr[1] }, b1[2] = { rr[2], rr[3] };
                mma16816(o[2 * dp], pf[kp], b0);
                mma16816(o[2 * dp + 1], pf[kp], b1);
            }
        }
        __syncthreads();
    }

    float inv0 = 1.f / l_run[0], inv1 = 1.f / l_run[1];
    long r0 = (long)(b * NN + mrow + g) * DD + h * 64;
    long r1 = (long)(b * NN + mrow + g + 8) * DD + h * 64;
    #pragma unroll
    for (int di = 0; di < 8; di++) {
        int col = di * 8 + 2 * tg;
        __nv_bfloat162 v0 = __floats2bfloat162_rn(o[di][0] * inv0, o[di][1] * inv0);
        __nv_bfloat162 v1 = __floats2bfloat162_rn(o[di][2] * inv1, o[di][3] * inv1);
        *(__nv_bfloat162*)&out[r0 + col] = v0;
        *(__nv_bfloat162*)&out[r1 + col] = v1;
    }
}

// ------------------------- generalized fast GEMM (cp.async + ldmatrix) ----------
struct GemmF {
    const __nv_bfloat16 *A, *B;
    long sA, sB, sC;
    long bBz;
    int K;
    void *C, *C2;
    int epi;                   // 0 exp bf16, 1 bf16, 3 residual fp32, 5 pair
    int zmode;
    const float *e0, *e1, *e2;
};

#define GF_SMEM (4*128*72*2)

__global__ void __launch_bounds__(256, 2) k_gemmF(GemmF p) {
    extern __shared__ __nv_bfloat16 smdyn[];
    __nv_bfloat16* sA[2] = { smdyn, smdyn + 128 * 72 };
    __nv_bfloat16* sB[2] = { smdyn + 2 * 128 * 72, smdyn + 3 * 128 * 72 };
    int tid = threadIdx.x, wid = tid >> 5, lane = tid & 31;
    int g = lane >> 2, tg = lane & 3;
    int bm = blockIdx.y * 128, bn = blockIdx.x * 128;
    int wm = (wid & 1) * 64, wn = (wid >> 1) * 32;

    int arow = lane & 15, ak = (lane & 16) ? 8 : 0;
    int brow = (lane & 7) + ((lane & 16) ? 8 : 0), bk = (lane & 8) ? 8 : 0;

    long offA = 0, offB = 0, offC = 0;
    if (p.zmode == 1) {
        int z = blockIdx.z, b = z >> 3, hc = z & 7;
        offA = (long)b * NN * DD + hc * 128;
        offB = (long)z * p.bBz;
        offC = offA;
    }
    const __nv_bfloat16* Ag = p.A + offA + (long)bm * p.sA;
    const __nv_bfloat16* Bg = p.B + offB + (long)bn * p.sB;

    float acc[4][4][4];
    #pragma unroll
    for (int i = 0; i < 4; i++)
        #pragma unroll
        for (int j = 0; j < 4; j++)
            #pragma unroll
            for (int q = 0; q < 4; q++) acc[i][j][q] = 0.f;

    #pragma unroll
    for (int t = 0; t < 4; t++) {
        int idx = tid + t * 256;
        int row = idx >> 3, v = (idx & 7) * 8;
        cp_async16(smem_u32(&sA[0][row * 72 + v]), Ag + (long)row * p.sA + v);
        cp_async16(smem_u32(&sB[0][row * 72 + v]), Bg + (long)row * p.sB + v);
    }
    asm volatile("cp.async.commit_group;");

    int nc = p.K >> 6;
    #pragma unroll 1
    for (int c = 0; c < nc; c++) {
        int s = c & 1;
        if (c < nc - 1) {
            int s2 = s ^ 1, k0 = (c + 1) * 64;
            #pragma unroll
            for (int t = 0; t < 4; t++) {
                int idx = tid + t * 256;
                int row = idx >> 3, v = (idx & 7) * 8;
                cp_async16(smem_u32(&sA[s2][row * 72 + v]), Ag + (long)row * p.sA + k0 + v);
                cp_async16(smem_u32(&sB[s2][row * 72 + v]), Bg + (long)row * p.sB + k0 + v);
            }
            asm volatile("cp.async.commit_group;");
            asm volatile("cp.async.wait_group 1;");
        } else {
            asm volatile("cp.async.wait_group 0;");
        }
        __syncthreads();

        const __nv_bfloat16* cA = sA[s];
        const __nv_bfloat16* cB = sB[s];
        #pragma unroll
        for (int kk = 0; kk < 64; kk += 16) {
            uint32_t ar[4][4], br[4][2];
            #pragma unroll
            for (int mi = 0; mi < 4; mi++)
                ldsm_x4(ar[mi], smem_u32(&cA[(wm + mi * 16 + arow) * 72 + kk + ak]));
            #pragma unroll
            for (int np = 0; np < 2; np++) {
                uint32_t rr[4];
                ldsm_x4(rr, smem_u32(&cB[(wn + np * 16 + brow) * 72 + kk + bk]));
                br[2 * np][0] = rr[0]; br[2 * np][1] = rr[1];
                br[2 * np + 1][0] = rr[2]; br[2 * np + 1][1] = rr[3];
            }
            #pragma unroll
            for (int mi = 0; mi < 4; mi++)
                #pragma unroll
                for (int ni = 0; ni < 4; ni++)
                    mma16816(acc[mi][ni], ar[mi], br[ni]);
        }
        __syncthreads();
    }

    #pragma unroll
    for (int mi = 0; mi < 4; mi++)
        #pragma unroll
        for (int ni = 0; ni < 4; ni++) {
            #pragma unroll
            for (int hh = 0; hh < 2; hh++) {
                int r = bm + wm + mi * 16 + g + hh * 8;
                int cc = bn + wn + ni * 8 + 2 * tg;
                float a0 = acc[mi][ni][2 * hh], a1 = acc[mi][ni][2 * hh + 1];
                int bb = r >> 11;
                if (p.epi == 0) {
                    float s0 = expf(p.e0[(long)bb * HID + cc]);
                    float s1 = expf(p.e0[(long)bb * HID + cc + 1]);
                    *(__nv_bfloat162*)&((__nv_bfloat16*)p.C)[offC + (long)r * p.sC + cc] =
                        __floats2bfloat162_rn(a0 * s0, a1 * s1);
                } else if (p.epi == 1) {
                    *(__nv_bfloat162*)&((__nv_bfloat16*)p.C)[offC + (long)r * p.sC + cc] =
                        __floats2bfloat162_rn(a0, a1);
                } else if (p.epi == 3) {
                    float2 res = *(const float2*)(p.e2 + (long)r * DD + cc);
                    float2 ov;
                    ov.x = res.x + a0 * p.e0[(long)bb * HID + cc] * p.e1[cc];
                    ov.y = res.y + a1 * p.e0[(long)bb * HID + cc + 1] * p.e1[cc + 1];
                    *(float2*)((float*)p.C + (long)r * p.sC + cc) = ov;
                } else {   // 5: pair
                    if (cc < 1024) {
                        float s0 = expf(p.e0[(long)bb * HID + cc]);
                        float s1 = expf(p.e0[(long)bb * HID + cc + 1]);
                        *(__nv_bfloat162*)&((__nv_bfloat16*)p.C)[(long)r * DD + cc] =
                            __floats2bfloat162_rn(a0 * s0, a1 * s1);
                    } else {
                        *(__nv_bfloat162*)&((__nv_bfloat16*)p.C2)[(long)r * DD + cc - 1024] =
                            __floats2bfloat162_rn(a0, a1);
                    }
                }
            }
        }
}

static cudaStream_t g_s2 = nullptr;
static cudaEvent_t g_evF = nullptr, g_evJ = nullptr;

static inline void init_attrs() {
    static int inited = 0;
    if (!inited) {
        cudaFuncSetAttribute(k_gemmF, cudaFuncAttributeMaxDynamicSharedMemorySize, GF_SMEM);
        cudaFuncSetAttribute(k_chS_red, cudaFuncAttributeMaxDynamicSharedMemorySize, CHR_SMEM);
        cudaStreamCreateWithFlags(&g_s2, cudaStreamNonBlocking);
        cudaEventCreateWithFlags(&g_evF, cudaEventDisableTiming);
        cudaEventCreateWithFlags(&g_evJ, cudaEventDisableTiming);
        inited = 1;
    }
}

static inline void rungemmF(const GemmF& p, int gx, int gy, int gz) {
    k_gemmF<<<dim3(gx, gy, gz), 256, GF_SMEM>>>(p);
}

#define SYMADDR(v, s) do { void* _p = nullptr; cudaGetSymbolAddress(&_p, s); v = (decltype(v))_p; } while (0)

// ------------------------- launch ----------------------------------------------
extern "C" void kernel_launch(void* const* d_in, const int* in_sizes, int n_in,
                              void* d_out, int out_size) {
    const float* x        = (const float*)d_in[0];
    const float* t        = (const float*)d_in[1];
    const float* n1s      = (const float*)d_in[2];
    const float* n1b      = (const float*)d_in[3];
    const float* n2s      = (const float*)d_in[4];
    const float* n2b      = (const float*)d_in[5];
    const float* tc_w1    = (const float*)d_in[6];
    const float* tc_b1    = (const float*)d_in[7];
    const float* tc_w2    = (const float*)d_in[8];
    const float* tc_b2    = (const float*)d_in[9];
    const float* tc_wa    = (const float*)d_in[10];
    const float* tc_ba    = (const float*)d_in[11];
    const float* tc_wc    = (const float*)d_in[12];
    const float* tc_bc    = (const float*)d_in[13];
    const float* attn_qk_w = (const float*)d_in[14];
    const float* attn_v_w  = (const float*)d_in[15];
    const float* attn_out_w= (const float*)d_in[16];
    const float* doob_w   = (const float*)d_in[17];
    const float* doob_b   = (const float*)d_in[18];
    const float* ch_qk_w  = (const float*)d_in[19];
    const float* ch_v_w   = (const float*)d_in[20];
    const float* ch_out_w = (const float*)d_in[21];
    const float* tau      = (const float*)d_in[22];
    const float* gamma1   = (const float*)d_in[23];
    const float* gamma2   = (const float*)d_in[24];

    float *emb, *p1, *p2, *p3, *av, *cv, *bias, *phi, *xmid;
    __nv_bfloat16 *wbf, *x1, *qkb, *vb, *attnb, *x2, *qkcb, *vcb, *Pcp, *chb;
    SYMADDR(emb, g_emb);   SYMADDR(p1, g_p1);     SYMADDR(p2, g_p2);  SYMADDR(p3, g_p3);
    SYMADDR(av, g_av);     SYMADDR(cv, g_cv);     SYMADDR(wbf, g_wbf);
    SYMADDR(x1, g_x1);     SYMADDR(qkb, g_qk);    SYMADDR(vb, g_v);
    SYMADDR(bias, g_bias); SYMADDR(phi, g_phi);
    SYMADDR(attnb, g_attn);SYMADDR(xmid, g_xmid); SYMADDR(x2, g_x2);
    SYMADDR(qkcb, g_qkc);  SYMADDR(vcb, g_vc);
    SYMADDR(Pcp, g_Pc);    SYMADDR(chb, g_ch);

    init_attrs();
    __nv_bfloat16* wqkv = wbf;
    __nv_bfloat16* wo   = wbf + 2 * 1048576;
    __nv_bfloat16* wcqv = wbf + 3 * 1048576;
    __nv_bfloat16* wco  = wbf + 5 * 1048576;

    // ---- fork: conditioning chain on side stream, weight convert on main -------
    cudaEventRecord(g_evF, 0);
    cudaStreamWaitEvent(g_s2, g_evF, 0);

    k_emb<<<(BB * HID + 255) / 256, 256, 0, g_s2>>>(t, emb);
    k_gemv_part<<<dim3(HID / 256, 64), 256, 0, g_s2>>>(emb, tc_w1, p1);
    k_gemv_step<<<dim3(HID / 256, 64, 1), 256, 0, g_s2>>>(p1, tc_b1, tc_w2, tc_w2, p2);
    k_gemv_step<<<dim3(HID / 256, 64, 2), 256, 0, g_s2>>>(p2, tc_b2, tc_wa, tc_wc, p3);
    k_gemv_red2<<<dim3((2 * HID + 255) / 256, 1, 2), 256, 0, g_s2>>>(p3, tc_ba, tc_bc, av, cv);
    cudaEventRecord(g_evJ, g_s2);

    k_convt<<<dim3(32, 32, 6), dim3(32, 8)>>>(attn_qk_w, attn_v_w, attn_out_w,
                                              ch_qk_w, ch_v_w, ch_out_w, wbf);
    cudaStreamWaitEvent(0, g_evJ, 0);   // join: main waits for conditioning

    // ---- token attention ----
    k_ln_mod<<<BN, 256>>>(x, x1, n1s, n1b, av, doob_w, doob_b, phi);
    {   // fused: qk = (x1@Wqk)*exp(a_lg) | v = x1@Wv
        GemmF p = {};
        p.A = x1; p.sA = DD; p.B = wqkv; p.sB = DD; p.K = DD;
        p.C = qkb; p.C2 = vb; p.sC = DD;
        p.epi = 5; p.e0 = av + 3072;
        rungemmF(p, 16, 32, 1);
    }
    k_bias<<<BB * HH * NN / 8, 256>>>(qkb, phi, bias);
    k_flash<<<dim3(1, 16, BB * HH), 256>>>(qkb, vb, bias, attnb);
    {   // x_mid = x + (attn @ Wo) * a_gate * gamma1
        GemmF p = {};
        p.A = attnb; p.sA = DD; p.B = wo; p.sB = DD; p.K = DD;
        p.C = xmid; p.sC = DD;
        p.epi = 3; p.e0 = av + 2048; p.e1 = gamma1; p.e2 = x;
        rungemmF(p, 8, 32, 1);
    }

    // ---- channel attention ----
    k_ln_mod<<<BN, 256>>>(xmid, x2, n2s, n2b, cv, nullptr, nullptr, nullptr);
    {   // fused: qkc | vc
        GemmF p = {};
        p.A = x2; p.sA = DD; p.B = wcqv; p.sB = DD; p.K = DD;
        p.C = qkcb; p.C2 = vcb; p.sC = DD;
        p.epi = 5; p.e0 = cv + 3072;
        rungemmF(p, 16, 32, 1);
    }
    k_chS_part<<<dim3(BB * HCC, 4), 256>>>(qkcb, p3);
    k_chS_red<<<BB * HCC, 256, CHR_SMEM>>>(p3, tau, Pcp);
    {   // ch[n][c] = sum_d Vc[n][d] * P[c][d]   (batched z = b*8+hc)
        GemmF p = {};
        p.A = vcb; p.sA = DD; p.B = Pcp; p.sB = 128; p.bBz = 128 * 128; p.K = 128;
        p.C = chb; p.sC = DD;
        p.epi = 1; p.zmode = 1;
        rungemmF(p, 1, 16, BB * HCC);
    }
    {   // out = x_mid + (ch @ Wco) * c_gate * gamma2
        GemmF p = {};
        p.A = chb; p.sA = DD; p.B = wco; p.sB = DD; p.K = DD;
        p.C = d_out; p.sC = DD;
        p.epi = 3; p.e0 = cv + 2048; p.e1 = gamma2; p.e2 = xmid;
        rungemmF(p, 8, 32, 1);
    }
}